// round 4
// baseline (speedup 1.0000x reference)
#include <cuda_runtime.h>
#include <cuda_fp16.h>

// Problem constants: N=100000, E=1600000, IN_C=16, HID=32, HEADS=2
#define MAXN 100000
#define MAXE 1600000
#define NEG 0.2f
#define INV_TEMP (1.0f / 0.7f)

// ---- device scratch (static; no allocations allowed) ----
__device__ __align__(16) __half g_xp[MAXN * 64];   // [N][64] projected features (fp16)
__device__ float g_asrc[MAXN * 2];                 // attention src logits per head
__device__ float g_adst[MAXN * 2];                 // attention dst logits per head
__device__ __align__(16) __half g_h[MAXN * 32];    // node embedding after GAT (fp16)
__device__ __align__(16) __half g_ps[MAXN * 32];   // h @ w1[0:32,:]  (fp16, gathered per edge)
__device__ __align__(16) float g_pd[MAXN * 32];    // h @ w1[32:64,:] (fp32, read once per node)
__device__ __align__(16) int2 g_se[MAXE];          // CSR payload: (src, edge_id) grouped by dst
__device__ int g_deg[MAXN];                        // in-degree histogram
__device__ int g_off[MAXN + 1];                    // CSR offsets
__device__ int g_cur[MAXN];                        // scatter cursors
__device__ int g_bsum[128];                        // scan block sums
__device__ int g_is64;

// K0: zero histogram; thread 0 detects int64 vs int32 edge storage
__global__ void k_init(const int* ei_words, int N) {
    int i = blockIdx.x * blockDim.x + threadIdx.x;
    if (i < N) g_deg[i] = 0;
    if (i == 0) {
        int nonzero = 0;
        #pragma unroll
        for (int j = 0; j < 64; j++)
            if (ei_words[2 * j + 1] != 0) nonzero++;
        g_is64 = (nonzero == 0) ? 1 : 0;
    }
}

// K0b: in-degree histogram (reads only dst half of the edge list)
__global__ void k_hist(const void* __restrict__ ei, int E) {
    int e = blockIdx.x * blockDim.x + threadIdx.x;
    if (e >= E) return;
    int d;
    if (g_is64) d = (int)((const long long*)ei)[e + E];
    else        d = ((const int*)ei)[e + E];
    atomicAdd(&g_deg[d], 1);
}

// Scan stage 1: per-block (1024) exclusive scan of g_deg -> g_off, block sums
__global__ void k_scan1(int N) {
    __shared__ int sh[1024];
    int tid = threadIdx.x;
    int i = blockIdx.x * 1024 + tid;
    int v = (i < N) ? g_deg[i] : 0;
    sh[tid] = v;
    __syncthreads();
    #pragma unroll
    for (int ofs = 1; ofs < 1024; ofs <<= 1) {
        int t = (tid >= ofs) ? sh[tid - ofs] : 0;
        __syncthreads();
        sh[tid] += t;
        __syncthreads();
    }
    if (i < N) g_off[i] = sh[tid] - v;
    if (tid == 1023) g_bsum[blockIdx.x] = sh[1023];
}

// Scan stage 2: exclusive scan of block sums (<=98) in one block
__global__ void k_scan2(int NB) {
    __shared__ int sh[128];
    int t = threadIdx.x;
    int v = (t < NB) ? g_bsum[t] : 0;
    sh[t] = v;
    __syncthreads();
    #pragma unroll
    for (int ofs = 1; ofs < 128; ofs <<= 1) {
        int tv = (t >= ofs) ? sh[t - ofs] : 0;
        __syncthreads();
        sh[t] += tv;
        __syncthreads();
    }
    if (t < NB) g_bsum[t] = sh[t] - v;
}

// Scan stage 3: add block bases; init cursors; sentinel
__global__ void k_scan3(int N, int E) {
    int i = blockIdx.x * blockDim.x + threadIdx.x;
    if (i < N) {
        int o = g_off[i] + g_bsum[i >> 10];
        g_off[i] = o;
        g_cur[i] = o;
    }
    if (i == 0) g_off[N] = E;
}

// Scatter (src, edge_id) into dst-grouped CSR
__global__ void k_scatter(const void* __restrict__ ei, int E) {
    int e = blockIdx.x * blockDim.x + threadIdx.x;
    if (e >= E) return;
    int s, d;
    if (g_is64) {
        const long long* p = (const long long*)ei;
        s = (int)p[e];
        d = (int)p[e + E];
    } else {
        const int* p = (const int*)ei;
        s = p[e];
        d = p[e + E];
    }
    int pos = atomicAdd(&g_cur[d], 1);
    g_se[pos] = make_int2(s, e);
}

// K1: per-node: xp = x@W (fp16 store), attention logits
__global__ void k1_node(const float* __restrict__ x, const float* __restrict__ W,
                        const float* __restrict__ att_src, const float* __restrict__ att_dst,
                        int N) {
    __shared__ float sW[16 * 64];
    __shared__ float sAs[64];
    __shared__ float sAd[64];
    int tid = threadIdx.x;
    for (int i = tid; i < 16 * 64; i += blockDim.x) sW[i] = W[i];
    if (tid < 64) { sAs[tid] = att_src[tid]; sAd[tid] = att_dst[tid]; }
    __syncthreads();

    int n = blockIdx.x * blockDim.x + tid;
    if (n >= N) return;

    float xv[16];
    const float4* x4 = (const float4*)(x + (size_t)n * 16);
    #pragma unroll
    for (int i = 0; i < 4; i++) {
        float4 t = x4[i];
        xv[4 * i + 0] = t.x; xv[4 * i + 1] = t.y;
        xv[4 * i + 2] = t.z; xv[4 * i + 3] = t.w;
    }

    float xp[64];
    float a0s = 0.f, a1s = 0.f, a0d = 0.f, a1d = 0.f;
    #pragma unroll
    for (int j = 0; j < 64; j++) {
        float v = 0.f;
        #pragma unroll
        for (int k = 0; k < 16; k++) v = fmaf(xv[k], sW[k * 64 + j], v);
        xp[j] = v;
        float as = sAs[j] * v;
        float ad = sAd[j] * v;
        if (j < 32) { a0s += as; a0d += ad; }
        else        { a1s += as; a1d += ad; }
    }

    g_asrc[n * 2 + 0] = a0s; g_asrc[n * 2 + 1] = a1s;
    g_adst[n * 2 + 0] = a0d; g_adst[n * 2 + 1] = a1d;

    union { uint4 u; __half2 h[4]; } pk;
    uint4* xpo = (uint4*)(g_xp + (size_t)n * 64);
    #pragma unroll
    for (int q = 0; q < 8; q++) {
        #pragma unroll
        for (int j = 0; j < 4; j++)
            pk.h[j] = __floats2half2_rn(xp[8 * q + 2 * j], xp[8 * q + 2 * j + 1]);
        xpo[q] = pk.u;
    }
}

// K2b: warp-per-destination GAT aggregation from CSR. Lane c owns channels
// {2c, 2c+1} (head = c/16). Register accumulators; softmax max-shift skipped.
__global__ void __launch_bounds__(256) k2b_aggregate(const float* __restrict__ bias, int N) {
    int n = (blockIdx.x * blockDim.x + threadIdx.x) >> 5;
    if (n >= N) return;
    int c = threadIdx.x & 31;
    int h = c >> 4;

    float adn = g_adst[n * 2 + h];
    float ee = g_asrc[n * 2 + h] + adn;           // self loop
    ee = ee > 0.f ? ee : NEG * ee;
    float w = __expf(ee);
    float2 xs = __half22float2(*(const __half2*)(g_xp + (size_t)n * 64 + 2 * c));
    float acc0 = w * xs.x, acc1 = w * xs.y, dsum = w;

    int i = g_off[n];
    int end = g_off[n + 1];

    for (; i + 4 <= end; i += 4) {
        int2 p0 = __ldg(&g_se[i]),     p1 = __ldg(&g_se[i + 1]);
        int2 p2 = __ldg(&g_se[i + 2]), p3 = __ldg(&g_se[i + 3]);
        int s0 = p0.x, s1 = p1.x, s2 = p2.x, s3 = p3.x;
        float a0 = g_asrc[s0 * 2 + h];
        float a1 = g_asrc[s1 * 2 + h];
        float a2 = g_asrc[s2 * 2 + h];
        float a3 = g_asrc[s3 * 2 + h];
        __half2 x0 = *(const __half2*)(g_xp + (size_t)s0 * 64 + 2 * c);
        __half2 x1 = *(const __half2*)(g_xp + (size_t)s1 * 64 + 2 * c);
        __half2 x2 = *(const __half2*)(g_xp + (size_t)s2 * 64 + 2 * c);
        __half2 x3 = *(const __half2*)(g_xp + (size_t)s3 * 64 + 2 * c);

        float e0 = a0 + adn; e0 = e0 > 0.f ? e0 : NEG * e0;
        float e1 = a1 + adn; e1 = e1 > 0.f ? e1 : NEG * e1;
        float e2 = a2 + adn; e2 = e2 > 0.f ? e2 : NEG * e2;
        float e3 = a3 + adn; e3 = e3 > 0.f ? e3 : NEG * e3;
        float w0 = __expf(e0), w1 = __expf(e1), w2 = __expf(e2), w3 = __expf(e3);
        dsum += (w0 + w1) + (w2 + w3);

        float2 f0 = __half22float2(x0);
        float2 f1 = __half22float2(x1);
        float2 f2 = __half22float2(x2);
        float2 f3 = __half22float2(x3);
        acc0 = fmaf(w0, f0.x, acc0); acc1 = fmaf(w0, f0.y, acc1);
        acc0 = fmaf(w1, f1.x, acc0); acc1 = fmaf(w1, f1.y, acc1);
        acc0 = fmaf(w2, f2.x, acc0); acc1 = fmaf(w2, f2.y, acc1);
        acc0 = fmaf(w3, f3.x, acc0); acc1 = fmaf(w3, f3.y, acc1);
    }
    for (; i < end; i++) {
        int s = __ldg(&g_se[i]).x;
        float a = g_asrc[s * 2 + h];
        __half2 xh = *(const __half2*)(g_xp + (size_t)s * 64 + 2 * c);
        float e0 = a + adn; e0 = e0 > 0.f ? e0 : NEG * e0;
        float w0 = __expf(e0);
        dsum += w0;
        float2 f = __half22float2(xh);
        acc0 = fmaf(w0, f.x, acc0);
        acc1 = fmaf(w0, f.y, acc1);
    }

    float d0 = __shfl_sync(0xFFFFFFFFu, dsum, 0);
    float d1 = __shfl_sync(0xFFFFFFFFu, dsum, 16);
    float p0 = __shfl_sync(0xFFFFFFFFu, acc0, (c + 16) & 31);
    float p1 = __shfl_sync(0xFFFFFFFFu, acc1, (c + 16) & 31);

    if (c < 16) {
        float h0 = 0.5f * (acc0 / d0 + p0 / d1) + bias[2 * c];
        float h1 = 0.5f * (acc1 / d0 + p1 / d1) + bias[2 * c + 1];
        *(__half2*)(g_h + (size_t)n * 32 + 2 * c) = __floats2half2_rn(h0, h1);
    }
}

// K3: fold MLP layer-1 into per-node partials (persistent warps, weights in regs)
__global__ void __launch_bounds__(256) k3_node_p(const float* __restrict__ w1, int N) {
    int c = threadIdx.x & 31;
    float wt[32], wb[32];
    #pragma unroll
    for (int k = 0; k < 32; k++) {
        wt[k] = __ldg(&w1[k * 32 + c]);
        wb[k] = __ldg(&w1[(32 + k) * 32 + c]);
    }

    int warpId = (blockIdx.x * blockDim.x + threadIdx.x) >> 5;
    int nWarps = (gridDim.x * blockDim.x) >> 5;

    for (int n = warpId; n < N; n += nWarps) {
        float h = __half2float(g_h[(size_t)n * 32 + c]);
        float ps = 0.f, pd = 0.f;
        #pragma unroll
        for (int k = 0; k < 32; k++) {
            float hk = __shfl_sync(0xFFFFFFFFu, h, k);
            ps = fmaf(hk, wt[k], ps);
            pd = fmaf(hk, wb[k], pd);
        }
        g_ps[(size_t)n * 32 + c] = __float2half_rn(ps);
        g_pd[(size_t)n * 32 + c] = pd;
    }
}

// K4b: edge MLP in CSR order. Warp per destination node: pd row in registers,
// per edge only ps[src] is gathered (64B/warp). Four edges reduced with a
// fused 9-shfl butterfly (sums land at lanes 0, 8, 16, 24).
__global__ void __launch_bounds__(256) k4b_edge_mlp(const float* __restrict__ b1,
                                                    const float* __restrict__ w2,
                                                    const float* __restrict__ b2,
                                                    float* __restrict__ out, int N) {
    int c = threadIdx.x & 31;
    float b1c = __ldg(&b1[c]);
    float w2c = __ldg(&w2[c]);
    float b2v = __ldg(&b2[0]);

    int warpId = (blockIdx.x * blockDim.x + threadIdx.x) >> 5;
    int nWarps = (gridDim.x * blockDim.x) >> 5;
    const unsigned FULL = 0xFFFFFFFFu;

    for (int n = warpId; n < N; n += nWarps) {
        int i = g_off[n];
        int end = g_off[n + 1];
        if (i >= end) continue;
        float base = g_pd[(size_t)n * 32 + c] + b1c;

        for (; i + 4 <= end; i += 4) {
            int2 e0 = __ldg(&g_se[i]),     e1 = __ldg(&g_se[i + 1]);
            int2 e2 = __ldg(&g_se[i + 2]), e3 = __ldg(&g_se[i + 3]);
            float v0 = fmaxf(__half2float(g_ps[(size_t)e0.x * 32 + c]) + base, 0.f) * w2c;
            float v1 = fmaxf(__half2float(g_ps[(size_t)e1.x * 32 + c]) + base, 0.f) * w2c;
            float v2 = fmaxf(__half2float(g_ps[(size_t)e2.x * 32 + c]) + base, 0.f) * w2c;
            float v3 = fmaxf(__half2float(g_ps[(size_t)e3.x * 32 + c]) + base, 0.f) * w2c;

            // fused 4-value butterfly reduce
            float a0 = v0 + __shfl_xor_sync(FULL, v0, 16);
            float a1 = v1 + __shfl_xor_sync(FULL, v1, 16);
            float a2 = v2 + __shfl_xor_sync(FULL, v2, 16);
            float a3 = v3 + __shfl_xor_sync(FULL, v3, 16);
            float bx = (c & 16) ? a2 : a0;
            float by = (c & 16) ? a3 : a1;
            bx += __shfl_xor_sync(FULL, bx, 8);
            by += __shfl_xor_sync(FULL, by, 8);
            float dd = (c & 8) ? by : bx;
            dd += __shfl_xor_sync(FULL, dd, 4);
            dd += __shfl_xor_sync(FULL, dd, 2);
            dd += __shfl_xor_sync(FULL, dd, 1);
            // lane 0 -> sum(v0), 8 -> v1, 16 -> v2, 24 -> v3
            if ((c & 7) == 0) {
                int sel = c >> 3;
                int eid = (sel == 0) ? e0.y : (sel == 1) ? e1.y : (sel == 2) ? e2.y : e3.y;
                out[eid] = (dd + b2v) * INV_TEMP;
            }
        }
        for (; i < end; i++) {
            int2 e0 = __ldg(&g_se[i]);
            float v = fmaxf(__half2float(g_ps[(size_t)e0.x * 32 + c]) + base, 0.f) * w2c;
            v += __shfl_xor_sync(FULL, v, 16);
            v += __shfl_xor_sync(FULL, v, 8);
            v += __shfl_xor_sync(FULL, v, 4);
            v += __shfl_xor_sync(FULL, v, 2);
            v += __shfl_xor_sync(FULL, v, 1);
            if (c == 0) out[e0.y] = (v + b2v) * INV_TEMP;
        }
    }
}

extern "C" void kernel_launch(void* const* d_in, const int* in_sizes, int n_in,
                              void* d_out, int out_size) {
    const float* x        = (const float*)d_in[0];
    const void*  ei       = d_in[1];
    const float* W        = (const float*)d_in[2];
    const float* att_src  = (const float*)d_in[3];
    const float* att_dst  = (const float*)d_in[4];
    const float* bias     = (const float*)d_in[5];
    const float* w1       = (const float*)d_in[6];
    const float* b1       = (const float*)d_in[7];
    const float* w2       = (const float*)d_in[8];
    const float* b2       = (const float*)d_in[9];
    float* out = (float*)d_out;

    int N = in_sizes[0] / 16;  // x is [N, 16]
    int E = in_sizes[1] / 2;   // edge_index is [2, E]
    int NB = (N + 1023) / 1024;

    k_init<<<(N + 255) / 256, 256>>>((const int*)ei, N);
    k_hist<<<(E + 255) / 256, 256>>>(ei, E);
    k_scan1<<<NB, 1024>>>(N);
    k_scan2<<<1, 128>>>(NB);
    k_scan3<<<NB, 1024>>>(N, E);
    k_scatter<<<(E + 255) / 256, 256>>>(ei, E);
    k1_node<<<(N + 127) / 128, 128>>>(x, W, att_src, att_dst, N);
    {
        long long T = (long long)N * 32;
        k2b_aggregate<<<(unsigned)((T + 255) / 256), 256>>>(bias, N);
    }
    k3_node_p<<<592, 256>>>(w1, N);
    k4b_edge_mlp<<<592, 256>>>(b1, w2, b2, out, N);
}

// round 5
// speedup vs baseline: 1.3975x; 1.3975x over previous
#include <cuda_runtime.h>
#include <cuda_fp16.h>

// Problem constants: N=100000, E=1600000, IN_C=16, HID=32, HEADS=2
#define MAXN 100000
#define MAXE 1600000
#define NEG 0.2f
#define INV_TEMP (1.0f / 0.7f)

// ---- device scratch (static; no allocations allowed) ----
__device__ __align__(16) __half g_xp[MAXN * 64];   // [N][64] projected features (fp16)
__device__ float g_asrc[MAXN * 2];                 // attention src logits per head
__device__ float g_adst[MAXN * 2];                 // attention dst logits per head
__device__ __align__(16) __half g_h[MAXN * 32];    // node embedding after GAT (fp16)
__device__ __align__(16) __half g_ps[MAXN * 32];   // h @ w1[0:32,:]  (fp16)
__device__ __align__(16) __half g_pd[MAXN * 32];   // h @ w1[32:64,:] (fp16)
__device__ __align__(16) int2 g_edge[MAXE];        // packed (src, dst)
__device__ __align__(16) int g_srcs[MAXE];         // CSR: src ids grouped by dst
__device__ int g_deg[MAXN];                        // in-degree histogram
__device__ int g_off[MAXN + 1];                    // CSR offsets
__device__ int g_cur[MAXN];                        // scatter cursors
__device__ int g_bsum[128];                        // scan block sums
__device__ int g_is64;

// K0: zero histogram; thread 0 also detects int64 vs int32 edge storage
__global__ void k_init(const int* ei_words, int N) {
    int i = blockIdx.x * blockDim.x + threadIdx.x;
    if (i < N) g_deg[i] = 0;
    if (i == 0) {
        int nonzero = 0;
        #pragma unroll
        for (int j = 0; j < 64; j++)
            if (ei_words[2 * j + 1] != 0) nonzero++;
        g_is64 = (nonzero == 0) ? 1 : 0;
    }
}

// K0b: pack edges to int2 and build in-degree histogram
__global__ void k0_pack(const void* __restrict__ ei, int E) {
    int e = blockIdx.x * blockDim.x + threadIdx.x;
    if (e >= E) return;
    int s, d;
    if (g_is64) {
        const long long* p = (const long long*)ei;
        s = (int)p[e];
        d = (int)p[e + E];
    } else {
        const int* p = (const int*)ei;
        s = p[e];
        d = p[e + E];
    }
    g_edge[e] = make_int2(s, d);
    atomicAdd(&g_deg[d], 1);
}

// Scan stage 1: per-block (1024) exclusive scan of g_deg -> g_off, block sums
__global__ void k_scan1(int N) {
    __shared__ int sh[1024];
    int tid = threadIdx.x;
    int i = blockIdx.x * 1024 + tid;
    int v = (i < N) ? g_deg[i] : 0;
    sh[tid] = v;
    __syncthreads();
    #pragma unroll
    for (int ofs = 1; ofs < 1024; ofs <<= 1) {
        int t = (tid >= ofs) ? sh[tid - ofs] : 0;
        __syncthreads();
        sh[tid] += t;
        __syncthreads();
    }
    if (i < N) g_off[i] = sh[tid] - v;
    if (tid == 1023) g_bsum[blockIdx.x] = sh[1023];
}

// Scan stage 2: exclusive scan of block sums (<=98) in one block
__global__ void k_scan2(int NB) {
    __shared__ int sh[128];
    int t = threadIdx.x;
    int v = (t < NB) ? g_bsum[t] : 0;
    sh[t] = v;
    __syncthreads();
    #pragma unroll
    for (int ofs = 1; ofs < 128; ofs <<= 1) {
        int tv = (t >= ofs) ? sh[t - ofs] : 0;
        __syncthreads();
        sh[t] += tv;
        __syncthreads();
    }
    if (t < NB) g_bsum[t] = sh[t] - v;
}

// Scan stage 3: add block bases; init cursors; sentinel
__global__ void k_scan3(int N, int E) {
    int i = blockIdx.x * blockDim.x + threadIdx.x;
    if (i < N) {
        int o = g_off[i] + g_bsum[i >> 10];
        g_off[i] = o;
        g_cur[i] = o;
    }
    if (i == 0) g_off[N] = E;
}

// Scatter edges into dst-grouped CSR
__global__ void k_scatter(int E) {
    int e = blockIdx.x * blockDim.x + threadIdx.x;
    if (e >= E) return;
    int2 sd = g_edge[e];
    int pos = atomicAdd(&g_cur[sd.y], 1);
    g_srcs[pos] = sd.x;
}

// K1: per-node: xp = x@W (fp16 store), attention logits
__global__ void k1_node(const float* __restrict__ x, const float* __restrict__ W,
                        const float* __restrict__ att_src, const float* __restrict__ att_dst,
                        int N) {
    __shared__ float sW[16 * 64];
    __shared__ float sAs[64];
    __shared__ float sAd[64];
    int tid = threadIdx.x;
    for (int i = tid; i < 16 * 64; i += blockDim.x) sW[i] = W[i];
    if (tid < 64) { sAs[tid] = att_src[tid]; sAd[tid] = att_dst[tid]; }
    __syncthreads();

    int n = blockIdx.x * blockDim.x + tid;
    if (n >= N) return;

    float xv[16];
    const float4* x4 = (const float4*)(x + (size_t)n * 16);
    #pragma unroll
    for (int i = 0; i < 4; i++) {
        float4 t = x4[i];
        xv[4 * i + 0] = t.x; xv[4 * i + 1] = t.y;
        xv[4 * i + 2] = t.z; xv[4 * i + 3] = t.w;
    }

    float xp[64];
    float a0s = 0.f, a1s = 0.f, a0d = 0.f, a1d = 0.f;
    #pragma unroll
    for (int j = 0; j < 64; j++) {
        float v = 0.f;
        #pragma unroll
        for (int k = 0; k < 16; k++) v = fmaf(xv[k], sW[k * 64 + j], v);
        xp[j] = v;
        float as = sAs[j] * v;
        float ad = sAd[j] * v;
        if (j < 32) { a0s += as; a0d += ad; }
        else        { a1s += as; a1d += ad; }
    }

    g_asrc[n * 2 + 0] = a0s; g_asrc[n * 2 + 1] = a1s;
    g_adst[n * 2 + 0] = a0d; g_adst[n * 2 + 1] = a1d;

    union { uint4 u; __half2 h[4]; } pk;
    uint4* xpo = (uint4*)(g_xp + (size_t)n * 64);
    #pragma unroll
    for (int q = 0; q < 8; q++) {
        #pragma unroll
        for (int j = 0; j < 4; j++)
            pk.h[j] = __floats2half2_rn(xp[8 * q + 2 * j], xp[8 * q + 2 * j + 1]);
        xpo[q] = pk.u;
    }
}

// K2b: warp-per-destination GAT aggregation from CSR. Lane c owns channels
// {2c, 2c+1} (head = c/16). Register accumulators; softmax max-shift skipped
// (shift-invariant; |e| small so exp cannot overflow).
__global__ void __launch_bounds__(256) k2b_aggregate(const float* __restrict__ bias, int N) {
    int n = (blockIdx.x * blockDim.x + threadIdx.x) >> 5;
    if (n >= N) return;
    int c = threadIdx.x & 31;
    int h = c >> 4;

    float adn = g_adst[n * 2 + h];
    float ee = g_asrc[n * 2 + h] + adn;           // self loop
    ee = ee > 0.f ? ee : NEG * ee;
    float w = __expf(ee);
    float2 xs = __half22float2(*(const __half2*)(g_xp + (size_t)n * 64 + 2 * c));
    float acc0 = w * xs.x, acc1 = w * xs.y, dsum = w;

    int i = g_off[n];
    int end = g_off[n + 1];

    for (; i + 4 <= end; i += 4) {
        int s0 = __ldg(&g_srcs[i]);
        int s1 = __ldg(&g_srcs[i + 1]);
        int s2 = __ldg(&g_srcs[i + 2]);
        int s3 = __ldg(&g_srcs[i + 3]);
        float a0 = g_asrc[s0 * 2 + h];
        float a1 = g_asrc[s1 * 2 + h];
        float a2 = g_asrc[s2 * 2 + h];
        float a3 = g_asrc[s3 * 2 + h];
        __half2 x0 = *(const __half2*)(g_xp + (size_t)s0 * 64 + 2 * c);
        __half2 x1 = *(const __half2*)(g_xp + (size_t)s1 * 64 + 2 * c);
        __half2 x2 = *(const __half2*)(g_xp + (size_t)s2 * 64 + 2 * c);
        __half2 x3 = *(const __half2*)(g_xp + (size_t)s3 * 64 + 2 * c);

        float e0 = a0 + adn; e0 = e0 > 0.f ? e0 : NEG * e0;
        float e1 = a1 + adn; e1 = e1 > 0.f ? e1 : NEG * e1;
        float e2 = a2 + adn; e2 = e2 > 0.f ? e2 : NEG * e2;
        float e3 = a3 + adn; e3 = e3 > 0.f ? e3 : NEG * e3;
        float w0 = __expf(e0), w1 = __expf(e1), w2 = __expf(e2), w3 = __expf(e3);
        dsum += (w0 + w1) + (w2 + w3);

        float2 f0 = __half22float2(x0);
        float2 f1 = __half22float2(x1);
        float2 f2 = __half22float2(x2);
        float2 f3 = __half22float2(x3);
        acc0 = fmaf(w0, f0.x, acc0); acc1 = fmaf(w0, f0.y, acc1);
        acc0 = fmaf(w1, f1.x, acc0); acc1 = fmaf(w1, f1.y, acc1);
        acc0 = fmaf(w2, f2.x, acc0); acc1 = fmaf(w2, f2.y, acc1);
        acc0 = fmaf(w3, f3.x, acc0); acc1 = fmaf(w3, f3.y, acc1);
    }
    for (; i < end; i++) {
        int s = __ldg(&g_srcs[i]);
        float a = g_asrc[s * 2 + h];
        __half2 xh = *(const __half2*)(g_xp + (size_t)s * 64 + 2 * c);
        float e0 = a + adn; e0 = e0 > 0.f ? e0 : NEG * e0;
        float w0 = __expf(e0);
        dsum += w0;
        float2 f = __half22float2(xh);
        acc0 = fmaf(w0, f.x, acc0);
        acc1 = fmaf(w0, f.y, acc1);
    }

    float d0 = __shfl_sync(0xFFFFFFFFu, dsum, 0);
    float d1 = __shfl_sync(0xFFFFFFFFu, dsum, 16);
    float p0 = __shfl_sync(0xFFFFFFFFu, acc0, (c + 16) & 31);
    float p1 = __shfl_sync(0xFFFFFFFFu, acc1, (c + 16) & 31);

    if (c < 16) {
        float h0 = 0.5f * (acc0 / d0 + p0 / d1) + bias[2 * c];
        float h1 = 0.5f * (acc1 / d0 + p1 / d1) + bias[2 * c + 1];
        *(__half2*)(g_h + (size_t)n * 32 + 2 * c) = __floats2half2_rn(h0, h1);
    }
}

// K3: fold MLP layer-1 into per-node partials (persistent warps, weights in regs)
__global__ void __launch_bounds__(256) k3_node_p(const float* __restrict__ w1, int N) {
    int c = threadIdx.x & 31;
    float wt[32], wb[32];
    #pragma unroll
    for (int k = 0; k < 32; k++) {
        wt[k] = __ldg(&w1[k * 32 + c]);
        wb[k] = __ldg(&w1[(32 + k) * 32 + c]);
    }

    int warpId = (blockIdx.x * blockDim.x + threadIdx.x) >> 5;
    int nWarps = (gridDim.x * blockDim.x) >> 5;

    for (int n = warpId; n < N; n += nWarps) {
        float h = __half2float(g_h[(size_t)n * 32 + c]);
        float ps = 0.f, pd = 0.f;
        #pragma unroll
        for (int k = 0; k < 32; k++) {
            float hk = __shfl_sync(0xFFFFFFFFu, h, k);
            ps = fmaf(hk, wt[k], ps);
            pd = fmaf(hk, wb[k], pd);
        }
        g_ps[(size_t)n * 32 + c] = __float2half_rn(ps);
        g_pd[(size_t)n * 32 + c] = __float2half_rn(pd);
    }
}

// K4: per-edge MLP in e-order (coalesced out). 4 lanes per edge, 8 hidden
// units per lane; fp16 gathers. Grid-stride with manual 2x unroll so two
// independent edges' gathers are in flight per thread.
__global__ void k4_edge_mlp(const float* __restrict__ b1, const float* __restrict__ w2,
                            const float* __restrict__ b2, float* __restrict__ out, int E) {
    int tid = blockIdx.x * blockDim.x + threadIdx.x;
    int q = tid & 3;
    float b1r[8], w2r[8];
    #pragma unroll
    for (int i = 0; i < 8; i++) {
        b1r[i] = __ldg(&b1[q * 8 + i]);
        w2r[i] = __ldg(&w2[q * 8 + i]);
    }
    float b2v = __ldg(&b2[0]);
    int step = (gridDim.x * blockDim.x) >> 2;
    const unsigned FULL = 0xFFFFFFFFu;

    for (int e = tid >> 2; e < E; e += 2 * step) {
        int e2 = e + step;
        bool has2 = e2 < E;
        int2 sdA = __ldg(&g_edge[e]);
        int2 sdB = has2 ? __ldg(&g_edge[e2]) : make_int2(0, 0);

        union { uint4 u; __half2 hh[4]; } aA, bA, aB, bB;
        aA.u = *((const uint4*)(g_ps + (size_t)sdA.x * 32) + q);
        bA.u = *((const uint4*)(g_pd + (size_t)sdA.y * 32) + q);
        aB.u = *((const uint4*)(g_ps + (size_t)sdB.x * 32) + q);
        bB.u = *((const uint4*)(g_pd + (size_t)sdB.y * 32) + q);

        float accA = 0.f, accB = 0.f;
        #pragma unroll
        for (int j = 0; j < 4; j++) {
            float2 faA = __half22float2(aA.hh[j]);
            float2 fbA = __half22float2(bA.hh[j]);
            float hA0 = fmaxf(faA.x + fbA.x + b1r[2 * j], 0.f);
            float hA1 = fmaxf(faA.y + fbA.y + b1r[2 * j + 1], 0.f);
            accA = fmaf(hA0, w2r[2 * j], accA);
            accA = fmaf(hA1, w2r[2 * j + 1], accA);
            float2 faB = __half22float2(aB.hh[j]);
            float2 fbB = __half22float2(bB.hh[j]);
            float hB0 = fmaxf(faB.x + fbB.x + b1r[2 * j], 0.f);
            float hB1 = fmaxf(faB.y + fbB.y + b1r[2 * j + 1], 0.f);
            accB = fmaf(hB0, w2r[2 * j], accB);
            accB = fmaf(hB1, w2r[2 * j + 1], accB);
        }
        accA += __shfl_xor_sync(FULL, accA, 1);
        accB += __shfl_xor_sync(FULL, accB, 1);
        accA += __shfl_xor_sync(FULL, accA, 2);
        accB += __shfl_xor_sync(FULL, accB, 2);
        if (q == 0) {
            out[e] = (accA + b2v) * INV_TEMP;
            if (has2) out[e2] = (accB + b2v) * INV_TEMP;
        }
    }
}

extern "C" void kernel_launch(void* const* d_in, const int* in_sizes, int n_in,
                              void* d_out, int out_size) {
    const float* x        = (const float*)d_in[0];
    const void*  ei       = d_in[1];
    const float* W        = (const float*)d_in[2];
    const float* att_src  = (const float*)d_in[3];
    const float* att_dst  = (const float*)d_in[4];
    const float* bias     = (const float*)d_in[5];
    const float* w1       = (const float*)d_in[6];
    const float* b1       = (const float*)d_in[7];
    const float* w2       = (const float*)d_in[8];
    const float* b2       = (const float*)d_in[9];
    float* out = (float*)d_out;

    int N = in_sizes[0] / 16;  // x is [N, 16]
    int E = in_sizes[1] / 2;   // edge_index is [2, E]
    int NB = (N + 1023) / 1024;

    k_init<<<(N + 255) / 256, 256>>>((const int*)ei, N);
    k0_pack<<<(E + 255) / 256, 256>>>(ei, E);
    k_scan1<<<NB, 1024>>>(N);
    k_scan2<<<1, 128>>>(NB);
    k_scan3<<<NB, 1024>>>(N, E);
    k_scatter<<<(E + 255) / 256, 256>>>(E);
    k1_node<<<(N + 127) / 128, 128>>>(x, W, att_src, att_dst, N);
    {
        long long T = (long long)N * 32;
        k2b_aggregate<<<(unsigned)((T + 255) / 256), 256>>>(bias, N);
    }
    k3_node_p<<<592, 256>>>(w1, N);
    k4_edge_mlp<<<1184, 256>>>(b1, w2, b2, out, E);
}

// round 6
// speedup vs baseline: 1.4011x; 1.0026x over previous
#include <cuda_runtime.h>
#include <cuda_fp16.h>

// Problem constants: N=100000, E=1600000, IN_C=16, HID=32, HEADS=2
#define MAXN 100000
#define MAXE 1600000
#define NEG 0.2f
#define INV_TEMP (1.0f / 0.7f)

// ---- device scratch (static; no allocations allowed) ----
__device__ __align__(16) __half g_xp[MAXN * 64];   // [N][64] projected features (fp16)
__device__ float g_asrc[MAXN * 2];                 // attention src logits per head
__device__ float g_adst[MAXN * 2];                 // attention dst logits per head
__device__ __align__(16) __half g_h[MAXN * 32];    // node embedding after GAT (fp16)
__device__ __align__(16) __half g_ps[MAXN * 32];   // h @ w1[0:32,:]  (fp16)
__device__ __align__(16) __half g_pd[MAXN * 32];   // h @ w1[32:64,:] (fp16)
__device__ __align__(16) int2 g_edge[MAXE];        // packed (src, dst)
__device__ __align__(16) int g_srcs[MAXE];         // CSR: src ids grouped by dst
__device__ int g_deg[MAXN];                        // in-degree histogram
__device__ int g_off[MAXN + 1];                    // CSR offsets
__device__ int g_cur[MAXN];                        // scatter cursors
__device__ int g_bsum[128];                        // scan block sums
__device__ int g_is64;

// K0: zero histogram; thread 0 also detects int64 vs int32 edge storage
__global__ void k_init(const int* ei_words, int N) {
    int i = blockIdx.x * blockDim.x + threadIdx.x;
    if (i < N) g_deg[i] = 0;
    if (i == 0) {
        int nonzero = 0;
        #pragma unroll
        for (int j = 0; j < 64; j++)
            if (ei_words[2 * j + 1] != 0) nonzero++;
        g_is64 = (nonzero == 0) ? 1 : 0;
    }
}

// K0b: pack edges to int2 and build in-degree histogram
__global__ void k0_pack(const void* __restrict__ ei, int E) {
    int e = blockIdx.x * blockDim.x + threadIdx.x;
    if (e >= E) return;
    int s, d;
    if (g_is64) {
        const long long* p = (const long long*)ei;
        s = (int)p[e];
        d = (int)p[e + E];
    } else {
        const int* p = (const int*)ei;
        s = p[e];
        d = p[e + E];
    }
    g_edge[e] = make_int2(s, d);
    atomicAdd(&g_deg[d], 1);
}

// Scan stage 1: per-block (1024) exclusive scan of g_deg -> g_off, block sums
__global__ void k_scan1(int N) {
    __shared__ int sh[1024];
    int tid = threadIdx.x;
    int i = blockIdx.x * 1024 + tid;
    int v = (i < N) ? g_deg[i] : 0;
    sh[tid] = v;
    __syncthreads();
    #pragma unroll
    for (int ofs = 1; ofs < 1024; ofs <<= 1) {
        int t = (tid >= ofs) ? sh[tid - ofs] : 0;
        __syncthreads();
        sh[tid] += t;
        __syncthreads();
    }
    if (i < N) g_off[i] = sh[tid] - v;
    if (tid == 1023) g_bsum[blockIdx.x] = sh[1023];
}

// Scan stage 2+3 merged: each block reduces the preceding block sums itself
// (NB <= 128), then adds the base, inits cursors, sets sentinel.
__global__ void k_scan3(int N, int E) {
    __shared__ int sred[4];
    int tid = threadIdx.x;
    if (tid < 128) {
        int v = (tid < blockIdx.x) ? g_bsum[tid] : 0;
        #pragma unroll
        for (int ofs = 16; ofs > 0; ofs >>= 1)
            v += __shfl_xor_sync(0xFFFFFFFFu, v, ofs);
        if ((tid & 31) == 0) sred[tid >> 5] = v;
    }
    __syncthreads();
    int base = sred[0] + sred[1] + sred[2] + sred[3];

    int i = blockIdx.x * 1024 + tid;
    if (i < N) {
        int o = g_off[i] + base;
        g_off[i] = o;
        g_cur[i] = o;
    }
    if (i == 0) g_off[N] = E;
}

// Scatter edges into dst-grouped CSR
__global__ void k_scatter(int E) {
    int e = blockIdx.x * blockDim.x + threadIdx.x;
    if (e >= E) return;
    int2 sd = g_edge[e];
    int pos = atomicAdd(&g_cur[sd.y], 1);
    g_srcs[pos] = sd.x;
}

// K1: per-node: xp = x@W (fp16 store), attention logits
__global__ void k1_node(const float* __restrict__ x, const float* __restrict__ W,
                        const float* __restrict__ att_src, const float* __restrict__ att_dst,
                        int N) {
    __shared__ float sW[16 * 64];
    __shared__ float sAs[64];
    __shared__ float sAd[64];
    int tid = threadIdx.x;
    for (int i = tid; i < 16 * 64; i += blockDim.x) sW[i] = W[i];
    if (tid < 64) { sAs[tid] = att_src[tid]; sAd[tid] = att_dst[tid]; }
    __syncthreads();

    int n = blockIdx.x * blockDim.x + tid;
    if (n >= N) return;

    float xv[16];
    const float4* x4 = (const float4*)(x + (size_t)n * 16);
    #pragma unroll
    for (int i = 0; i < 4; i++) {
        float4 t = x4[i];
        xv[4 * i + 0] = t.x; xv[4 * i + 1] = t.y;
        xv[4 * i + 2] = t.z; xv[4 * i + 3] = t.w;
    }

    float xp[64];
    float a0s = 0.f, a1s = 0.f, a0d = 0.f, a1d = 0.f;
    #pragma unroll
    for (int j = 0; j < 64; j++) {
        float v = 0.f;
        #pragma unroll
        for (int k = 0; k < 16; k++) v = fmaf(xv[k], sW[k * 64 + j], v);
        xp[j] = v;
        float as = sAs[j] * v;
        float ad = sAd[j] * v;
        if (j < 32) { a0s += as; a0d += ad; }
        else        { a1s += as; a1d += ad; }
    }

    g_asrc[n * 2 + 0] = a0s; g_asrc[n * 2 + 1] = a1s;
    g_adst[n * 2 + 0] = a0d; g_adst[n * 2 + 1] = a1d;

    union { uint4 u; __half2 h[4]; } pk;
    uint4* xpo = (uint4*)(g_xp + (size_t)n * 64);
    #pragma unroll
    for (int q = 0; q < 8; q++) {
        #pragma unroll
        for (int j = 0; j < 4; j++)
            pk.h[j] = __floats2half2_rn(xp[8 * q + 2 * j], xp[8 * q + 2 * j + 1]);
        xpo[q] = pk.u;
    }
}

// K2b: warp-per-destination GAT aggregation from CSR, unroll-8 gather batches.
// Lane c owns channels {2c, 2c+1} (head = c/16). Softmax max-shift skipped
// (shift-invariant; |e| small so exp cannot overflow).
__global__ void __launch_bounds__(256) k2b_aggregate(const float* __restrict__ bias, int N) {
    int n = (blockIdx.x * blockDim.x + threadIdx.x) >> 5;
    if (n >= N) return;
    int c = threadIdx.x & 31;
    int h = c >> 4;

    float adn = g_adst[n * 2 + h];
    float ee = g_asrc[n * 2 + h] + adn;           // self loop
    ee = ee > 0.f ? ee : NEG * ee;
    float w = __expf(ee);
    float2 xs = __half22float2(*(const __half2*)(g_xp + (size_t)n * 64 + 2 * c));
    float acc0 = w * xs.x, acc1 = w * xs.y, dsum = w;

    int i = g_off[n];
    int end = g_off[n + 1];

    for (; i + 8 <= end; i += 8) {
        int s[8];
        #pragma unroll
        for (int j = 0; j < 8; j++) s[j] = __ldg(&g_srcs[i + j]);
        float a[8];
        __half2 xh[8];
        #pragma unroll
        for (int j = 0; j < 8; j++) {
            a[j] = __ldg(&g_asrc[s[j] * 2 + h]);
            xh[j] = *(const __half2*)(g_xp + (size_t)s[j] * 64 + 2 * c);
        }
        #pragma unroll
        for (int j = 0; j < 8; j++) {
            float e0 = a[j] + adn; e0 = e0 > 0.f ? e0 : NEG * e0;
            float w0 = __expf(e0);
            dsum += w0;
            float2 f = __half22float2(xh[j]);
            acc0 = fmaf(w0, f.x, acc0);
            acc1 = fmaf(w0, f.y, acc1);
        }
    }
    for (; i + 2 <= end; i += 2) {
        int s0 = __ldg(&g_srcs[i]), s1 = __ldg(&g_srcs[i + 1]);
        float a0 = __ldg(&g_asrc[s0 * 2 + h]);
        float a1 = __ldg(&g_asrc[s1 * 2 + h]);
        __half2 x0 = *(const __half2*)(g_xp + (size_t)s0 * 64 + 2 * c);
        __half2 x1 = *(const __half2*)(g_xp + (size_t)s1 * 64 + 2 * c);
        float e0 = a0 + adn; e0 = e0 > 0.f ? e0 : NEG * e0;
        float e1 = a1 + adn; e1 = e1 > 0.f ? e1 : NEG * e1;
        float w0 = __expf(e0), w1 = __expf(e1);
        dsum += w0 + w1;
        float2 f0 = __half22float2(x0);
        float2 f1 = __half22float2(x1);
        acc0 = fmaf(w0, f0.x, acc0); acc1 = fmaf(w0, f0.y, acc1);
        acc0 = fmaf(w1, f1.x, acc0); acc1 = fmaf(w1, f1.y, acc1);
    }
    if (i < end) {
        int s = __ldg(&g_srcs[i]);
        float a = __ldg(&g_asrc[s * 2 + h]);
        __half2 xh = *(const __half2*)(g_xp + (size_t)s * 64 + 2 * c);
        float e0 = a + adn; e0 = e0 > 0.f ? e0 : NEG * e0;
        float w0 = __expf(e0);
        dsum += w0;
        float2 f = __half22float2(xh);
        acc0 = fmaf(w0, f.x, acc0);
        acc1 = fmaf(w0, f.y, acc1);
    }

    float d0 = __shfl_sync(0xFFFFFFFFu, dsum, 0);
    float d1 = __shfl_sync(0xFFFFFFFFu, dsum, 16);
    float p0 = __shfl_sync(0xFFFFFFFFu, acc0, (c + 16) & 31);
    float p1 = __shfl_sync(0xFFFFFFFFu, acc1, (c + 16) & 31);

    if (c < 16) {
        float h0 = 0.5f * (acc0 / d0 + p0 / d1) + bias[2 * c];
        float h1 = 0.5f * (acc1 / d0 + p1 / d1) + bias[2 * c + 1];
        *(__half2*)(g_h + (size_t)n * 32 + 2 * c) = __floats2half2_rn(h0, h1);
    }
}

// K3: fold MLP layer-1 into per-node partials (persistent warps, weights in regs)
__global__ void __launch_bounds__(256) k3_node_p(const float* __restrict__ w1, int N) {
    int c = threadIdx.x & 31;
    float wt[32], wb[32];
    #pragma unroll
    for (int k = 0; k < 32; k++) {
        wt[k] = __ldg(&w1[k * 32 + c]);
        wb[k] = __ldg(&w1[(32 + k) * 32 + c]);
    }

    int warpId = (blockIdx.x * blockDim.x + threadIdx.x) >> 5;
    int nWarps = (gridDim.x * blockDim.x) >> 5;

    for (int n = warpId; n < N; n += nWarps) {
        float h = __half2float(g_h[(size_t)n * 32 + c]);
        float ps = 0.f, pd = 0.f;
        #pragma unroll
        for (int k = 0; k < 32; k++) {
            float hk = __shfl_sync(0xFFFFFFFFu, h, k);
            ps = fmaf(hk, wt[k], ps);
            pd = fmaf(hk, wb[k], pd);
        }
        g_ps[(size_t)n * 32 + c] = __float2half_rn(ps);
        g_pd[(size_t)n * 32 + c] = __float2half_rn(pd);
    }
}

// K4: per-edge MLP. Each 4-lane group owns a consecutive edge PAIR (one int4
// edge load); two independent pairs per iteration (4 edges of gathers in
// flight). Fused pair reduce: sums land on lanes q==0 / q==1 of the group;
// both store adjacent 4B (coalesced).
__device__ __forceinline__ float mlp_quarter(const uint4 a, const uint4 b,
                                             const float* b1r, const float* w2r) {
    union { uint4 u; __half2 hh[4]; } ua, ub;
    ua.u = a; ub.u = b;
    float acc = 0.f;
    #pragma unroll
    for (int j = 0; j < 4; j++) {
        float2 fa = __half22float2(ua.hh[j]);
        float2 fb = __half22float2(ub.hh[j]);
        float h0 = fmaxf(fa.x + fb.x + b1r[2 * j], 0.f);
        float h1 = fmaxf(fa.y + fb.y + b1r[2 * j + 1], 0.f);
        acc = fmaf(h0, w2r[2 * j], acc);
        acc = fmaf(h1, w2r[2 * j + 1], acc);
    }
    return acc;
}

__global__ void __launch_bounds__(256) k4_edge_mlp(const float* __restrict__ b1,
                                                   const float* __restrict__ w2,
                                                   const float* __restrict__ b2,
                                                   float* __restrict__ out, int E) {
    int tid = blockIdx.x * blockDim.x + threadIdx.x;
    int q = tid & 3;
    float b1r[8], w2r[8];
    #pragma unroll
    for (int i = 0; i < 8; i++) {
        b1r[i] = __ldg(&b1[q * 8 + i]);
        w2r[i] = __ldg(&w2[q * 8 + i]);
    }
    float b2v = __ldg(&b2[0]);
    const unsigned FULL = 0xFFFFFFFFu;

    int nGroups = (gridDim.x * blockDim.x) >> 2;
    int nPairs = (E + 1) >> 1;

    for (int p = tid >> 2; p < nPairs; p += 2 * nGroups) {
        int pB = p + nGroups;
        bool hasB = pB < nPairs;
        int eA = 2 * p, eB = 2 * pB;

        int4 edA = __ldg((const int4*)(g_edge + eA));                  // (sA0,dA0,sA1,dA1)
        int4 edB = hasB ? __ldg((const int4*)(g_edge + eB)) : make_int4(0, 0, 0, 0);

        uint4 psA0 = *((const uint4*)(g_ps + (size_t)edA.x * 32) + q);
        uint4 pdA0 = *((const uint4*)(g_pd + (size_t)edA.y * 32) + q);
        uint4 psA1 = *((const uint4*)(g_ps + (size_t)edA.z * 32) + q);
        uint4 pdA1 = *((const uint4*)(g_pd + (size_t)edA.w * 32) + q);
        uint4 psB0 = *((const uint4*)(g_ps + (size_t)edB.x * 32) + q);
        uint4 pdB0 = *((const uint4*)(g_pd + (size_t)edB.y * 32) + q);
        uint4 psB1 = *((const uint4*)(g_ps + (size_t)edB.z * 32) + q);
        uint4 pdB1 = *((const uint4*)(g_pd + (size_t)edB.w * 32) + q);

        float vA0 = mlp_quarter(psA0, pdA0, b1r, w2r);
        float vA1 = mlp_quarter(psA1, pdA1, b1r, w2r);
        float vB0 = mlp_quarter(psB0, pdB0, b1r, w2r);
        float vB1 = mlp_quarter(psB1, pdB1, b1r, w2r);

        // fused pair reduce: after xor1 + select + xor2, lane q==0 holds
        // sum(v*0), lane q==1 holds sum(v*1)
        float a0 = vA0 + __shfl_xor_sync(FULL, vA0, 1);
        float a1 = vA1 + __shfl_xor_sync(FULL, vA1, 1);
        float mA = (q & 1) ? a1 : a0;
        mA += __shfl_xor_sync(FULL, mA, 2);

        float c0 = vB0 + __shfl_xor_sync(FULL, vB0, 1);
        float c1 = vB1 + __shfl_xor_sync(FULL, vB1, 1);
        float mB = (q & 1) ? c1 : c0;
        mB += __shfl_xor_sync(FULL, mB, 2);

        if (q < 2) {
            int e = eA + q;
            if (e < E) out[e] = (mA + b2v) * INV_TEMP;
            if (hasB) {
                int e2 = eB + q;
                if (e2 < E) out[e2] = (mB + b2v) * INV_TEMP;
            }
        }
    }
}

extern "C" void kernel_launch(void* const* d_in, const int* in_sizes, int n_in,
                              void* d_out, int out_size) {
    const float* x        = (const float*)d_in[0];
    const void*  ei       = d_in[1];
    const float* W        = (const float*)d_in[2];
    const float* att_src  = (const float*)d_in[3];
    const float* att_dst  = (const float*)d_in[4];
    const float* bias     = (const float*)d_in[5];
    const float* w1       = (const float*)d_in[6];
    const float* b1       = (const float*)d_in[7];
    const float* w2       = (const float*)d_in[8];
    const float* b2       = (const float*)d_in[9];
    float* out = (float*)d_out;

    int N = in_sizes[0] / 16;  // x is [N, 16]
    int E = in_sizes[1] / 2;   // edge_index is [2, E]
    int NB = (N + 1023) / 1024;

    k_init<<<(N + 255) / 256, 256>>>((const int*)ei, N);
    k0_pack<<<(E + 255) / 256, 256>>>(ei, E);
    k_scan1<<<NB, 1024>>>(N);
    k_scan3<<<NB, 1024>>>(N, E);
    k_scatter<<<(E + 255) / 256, 256>>>(E);
    k1_node<<<(N + 127) / 128, 128>>>(x, W, att_src, att_dst, N);
    {
        long long T = (long long)N * 32;
        k2b_aggregate<<<(unsigned)((T + 255) / 256), 256>>>(bias, N);
    }
    k3_node_p<<<592, 256>>>(w1, N);
    k4_edge_mlp<<<1184, 256>>>(b1, w2, b2, out, E);
}

// round 7
// speedup vs baseline: 1.4359x; 1.0248x over previous
#include <cuda_runtime.h>
#include <cuda_fp16.h>

// Problem constants: N=100000, E=1600000, IN_C=16, HID=32, HEADS=2
#define MAXN 100000
#define MAXE 1600000
#define NEG 0.2f
#define INV_TEMP (1.0f / 0.7f)

// ---- device scratch (static; no allocations allowed) ----
__device__ __align__(16) __half g_xp[MAXN * 64];   // [N][64] projected features (fp16)
__device__ float g_asrc[MAXN * 2];                 // attention src logits per head
__device__ float g_adst[MAXN * 2];                 // attention dst logits per head
__device__ __align__(16) __half g_h[MAXN * 32];    // node embedding after GAT (fp16)
__device__ __align__(16) __half g_ps[MAXN * 32];   // h @ w1[0:32,:]  (fp16)
__device__ __align__(16) __half g_pd[MAXN * 32];   // h @ w1[32:64,:] (fp16)
__device__ __align__(16) int2 g_edge[MAXE];        // packed (src, dst)
__device__ __align__(16) int g_srcs[MAXE];         // CSR: src ids grouped by dst
__device__ int g_deg[MAXN];                        // in-degree histogram
__device__ int g_off[MAXN + 1];                    // CSR offsets
__device__ int g_cur[MAXN];                        // scatter cursors
__device__ int g_bsum[128];                        // scan block totals
__device__ int g_bflag[128];                       // scan publish flags
__device__ int g_is64;

// KA: fused init + node projection.
//  - zeroes g_deg and scan flags
//  - thread 0 detects int64 vs int32 edge storage
//  - computes xp = x@W (fp16 store) and attention logits per node
__global__ void kA_init_node(const int* __restrict__ ei_words,
                             const float* __restrict__ x, const float* __restrict__ W,
                             const float* __restrict__ att_src, const float* __restrict__ att_dst,
                             int N) {
    __shared__ float sW[16 * 64];
    __shared__ float sAs[64];
    __shared__ float sAd[64];
    int tid = threadIdx.x;
    for (int i = tid; i < 16 * 64; i += blockDim.x) sW[i] = W[i];
    if (tid < 64) { sAs[tid] = att_src[tid]; sAd[tid] = att_dst[tid]; }

    int n = blockIdx.x * blockDim.x + tid;
    if (n < N) g_deg[n] = 0;
    if (n < 128) { g_bflag[n] = 0; }
    if (n == 0) {
        int nonzero = 0;
        #pragma unroll
        for (int j = 0; j < 64; j++)
            if (ei_words[2 * j + 1] != 0) nonzero++;
        g_is64 = (nonzero == 0) ? 1 : 0;
    }
    __syncthreads();
    if (n >= N) return;

    float xv[16];
    const float4* x4 = (const float4*)(x + (size_t)n * 16);
    #pragma unroll
    for (int i = 0; i < 4; i++) {
        float4 t = x4[i];
        xv[4 * i + 0] = t.x; xv[4 * i + 1] = t.y;
        xv[4 * i + 2] = t.z; xv[4 * i + 3] = t.w;
    }

    float xp[64];
    float a0s = 0.f, a1s = 0.f, a0d = 0.f, a1d = 0.f;
    #pragma unroll
    for (int j = 0; j < 64; j++) {
        float v = 0.f;
        #pragma unroll
        for (int k = 0; k < 16; k++) v = fmaf(xv[k], sW[k * 64 + j], v);
        xp[j] = v;
        float as = sAs[j] * v;
        float ad = sAd[j] * v;
        if (j < 32) { a0s += as; a0d += ad; }
        else        { a1s += as; a1d += ad; }
    }

    g_asrc[n * 2 + 0] = a0s; g_asrc[n * 2 + 1] = a1s;
    g_adst[n * 2 + 0] = a0d; g_adst[n * 2 + 1] = a1d;

    union { uint4 u; __half2 h[4]; } pk;
    uint4* xpo = (uint4*)(g_xp + (size_t)n * 64);
    #pragma unroll
    for (int q = 0; q < 8; q++) {
        #pragma unroll
        for (int j = 0; j < 4; j++)
            pk.h[j] = __floats2half2_rn(xp[8 * q + 2 * j], xp[8 * q + 2 * j + 1]);
        xpo[q] = pk.u;
    }
}

// K0b: pack edges to int2 and build in-degree histogram
__global__ void k0_pack(const void* __restrict__ ei, int E) {
    int e = blockIdx.x * blockDim.x + threadIdx.x;
    if (e >= E) return;
    int s, d;
    if (g_is64) {
        const long long* p = (const long long*)ei;
        s = (int)p[e];
        d = (int)p[e + E];
    } else {
        const int* p = (const int*)ei;
        s = p[e];
        d = p[e + E];
    }
    g_edge[e] = make_int2(s, d);
    atomicAdd(&g_deg[d], 1);
}

// K_scan: single-kernel exclusive scan of g_deg -> g_off (+ cursor init,
// sentinel). Warp-shuffle block scan; cross-block base via parallel lookback
// (block b sums all predecessor totals; all <=98 blocks are co-resident so
// the spin-wait always makes progress).
__global__ void __launch_bounds__(1024) k_scan(int N, int E) {
    __shared__ int warpsums[32];
    __shared__ int sred[32];
    __shared__ int sbase;
    const unsigned FULL = 0xFFFFFFFFu;
    int tid = threadIdx.x;
    int lane = tid & 31, wid = tid >> 5;
    int b = blockIdx.x;
    int i = b * 1024 + tid;

    int v = (i < N) ? g_deg[i] : 0;
    // warp inclusive scan
    int sc = v;
    #pragma unroll
    for (int ofs = 1; ofs < 32; ofs <<= 1) {
        int t = __shfl_up_sync(FULL, sc, ofs);
        if (lane >= ofs) sc += t;
    }
    if (lane == 31) warpsums[wid] = sc;
    __syncthreads();
    if (wid == 0) {
        int w = warpsums[lane];
        #pragma unroll
        for (int ofs = 1; ofs < 32; ofs <<= 1) {
            int t = __shfl_up_sync(FULL, w, ofs);
            if (lane >= ofs) w += t;
        }
        warpsums[lane] = w;
    }
    __syncthreads();
    int blockpref = (wid > 0) ? warpsums[wid - 1] : 0;
    int excl = sc + blockpref - v;       // exclusive within block
    int total = warpsums[31];

    // publish this block's total
    if (tid == 0) {
        g_bsum[b] = total;
        __threadfence();
        atomicExch(&g_bflag[b], 1);
    }

    // parallel lookback: thread t (< b) fetches block t's total
    int part = 0;
    if (tid < b) {
        while (atomicAdd(&g_bflag[tid], 0) == 0) { }
        __threadfence();
        part = g_bsum[tid];
    }
    #pragma unroll
    for (int ofs = 16; ofs > 0; ofs >>= 1)
        part += __shfl_xor_sync(FULL, part, ofs);
    if (lane == 0) sred[wid] = part;
    __syncthreads();
    if (tid == 0) {
        int s = 0;
        #pragma unroll
        for (int k = 0; k < 4; k++) s += sred[k];   // b <= 97 -> warps 0..3 only
        sbase = s;
    }
    __syncthreads();
    int base = sbase;

    if (i < N) {
        int o = excl + base;
        g_off[i] = o;
        g_cur[i] = o;
    }
    if (b == 0 && tid == 0) g_off[N] = E;
}

// Scatter edges into dst-grouped CSR
__global__ void k_scatter(int E) {
    int e = blockIdx.x * blockDim.x + threadIdx.x;
    if (e >= E) return;
    int2 sd = g_edge[e];
    int pos = atomicAdd(&g_cur[sd.y], 1);
    g_srcs[pos] = sd.x;
}

// K2b: warp-per-destination GAT aggregation from CSR, unroll-8 gather batches.
// Lane c owns channels {2c, 2c+1} (head = c/16). Softmax max-shift skipped
// (shift-invariant; |e| small so exp cannot overflow).
__global__ void __launch_bounds__(256) k2b_aggregate(const float* __restrict__ bias, int N) {
    int n = (blockIdx.x * blockDim.x + threadIdx.x) >> 5;
    if (n >= N) return;
    int c = threadIdx.x & 31;
    int h = c >> 4;

    float adn = g_adst[n * 2 + h];
    float ee = g_asrc[n * 2 + h] + adn;           // self loop
    ee = ee > 0.f ? ee : NEG * ee;
    float w = __expf(ee);
    float2 xs = __half22float2(*(const __half2*)(g_xp + (size_t)n * 64 + 2 * c));
    float acc0 = w * xs.x, acc1 = w * xs.y, dsum = w;

    int i = g_off[n];
    int end = g_off[n + 1];

    for (; i + 8 <= end; i += 8) {
        int s[8];
        #pragma unroll
        for (int j = 0; j < 8; j++) s[j] = __ldg(&g_srcs[i + j]);
        float a[8];
        __half2 xh[8];
        #pragma unroll
        for (int j = 0; j < 8; j++) {
            a[j] = __ldg(&g_asrc[s[j] * 2 + h]);
            xh[j] = *(const __half2*)(g_xp + (size_t)s[j] * 64 + 2 * c);
        }
        #pragma unroll
        for (int j = 0; j < 8; j++) {
            float e0 = a[j] + adn; e0 = e0 > 0.f ? e0 : NEG * e0;
            float w0 = __expf(e0);
            dsum += w0;
            float2 f = __half22float2(xh[j]);
            acc0 = fmaf(w0, f.x, acc0);
            acc1 = fmaf(w0, f.y, acc1);
        }
    }
    for (; i + 2 <= end; i += 2) {
        int s0 = __ldg(&g_srcs[i]), s1 = __ldg(&g_srcs[i + 1]);
        float a0 = __ldg(&g_asrc[s0 * 2 + h]);
        float a1 = __ldg(&g_asrc[s1 * 2 + h]);
        __half2 x0 = *(const __half2*)(g_xp + (size_t)s0 * 64 + 2 * c);
        __half2 x1 = *(const __half2*)(g_xp + (size_t)s1 * 64 + 2 * c);
        float e0 = a0 + adn; e0 = e0 > 0.f ? e0 : NEG * e0;
        float e1 = a1 + adn; e1 = e1 > 0.f ? e1 : NEG * e1;
        float w0 = __expf(e0), w1 = __expf(e1);
        dsum += w0 + w1;
        float2 f0 = __half22float2(x0);
        float2 f1 = __half22float2(x1);
        acc0 = fmaf(w0, f0.x, acc0); acc1 = fmaf(w0, f0.y, acc1);
        acc0 = fmaf(w1, f1.x, acc0); acc1 = fmaf(w1, f1.y, acc1);
    }
    if (i < end) {
        int s = __ldg(&g_srcs[i]);
        float a = __ldg(&g_asrc[s * 2 + h]);
        __half2 xh = *(const __half2*)(g_xp + (size_t)s * 64 + 2 * c);
        float e0 = a + adn; e0 = e0 > 0.f ? e0 : NEG * e0;
        float w0 = __expf(e0);
        dsum += w0;
        float2 f = __half22float2(xh);
        acc0 = fmaf(w0, f.x, acc0);
        acc1 = fmaf(w0, f.y, acc1);
    }

    float d0 = __shfl_sync(0xFFFFFFFFu, dsum, 0);
    float d1 = __shfl_sync(0xFFFFFFFFu, dsum, 16);
    float p0 = __shfl_sync(0xFFFFFFFFu, acc0, (c + 16) & 31);
    float p1 = __shfl_sync(0xFFFFFFFFu, acc1, (c + 16) & 31);

    if (c < 16) {
        float h0 = 0.5f * (acc0 / d0 + p0 / d1) + bias[2 * c];
        float h1 = 0.5f * (acc1 / d0 + p1 / d1) + bias[2 * c + 1];
        *(__half2*)(g_h + (size_t)n * 32 + 2 * c) = __floats2half2_rn(h0, h1);
    }
}

// K3: fold MLP layer-1 into per-node partials (persistent warps, weights in regs)
__global__ void __launch_bounds__(256) k3_node_p(const float* __restrict__ w1, int N) {
    int c = threadIdx.x & 31;
    float wt[32], wb[32];
    #pragma unroll
    for (int k = 0; k < 32; k++) {
        wt[k] = __ldg(&w1[k * 32 + c]);
        wb[k] = __ldg(&w1[(32 + k) * 32 + c]);
    }

    int warpId = (blockIdx.x * blockDim.x + threadIdx.x) >> 5;
    int nWarps = (gridDim.x * blockDim.x) >> 5;

    for (int n = warpId; n < N; n += nWarps) {
        float h = __half2float(g_h[(size_t)n * 32 + c]);
        float ps = 0.f, pd = 0.f;
        #pragma unroll
        for (int k = 0; k < 32; k++) {
            float hk = __shfl_sync(0xFFFFFFFFu, h, k);
            ps = fmaf(hk, wt[k], ps);
            pd = fmaf(hk, wb[k], pd);
        }
        g_ps[(size_t)n * 32 + c] = __float2half_rn(ps);
        g_pd[(size_t)n * 32 + c] = __float2half_rn(pd);
    }
}

// K4: per-edge MLP. 4-lane group per consecutive edge pair (one int4 edge
// load); two independent pairs in flight per thread. ps+pd summed in half2
// (saves FMA-pipe ops); b1/relu/dot in fp32.
__device__ __forceinline__ float mlp_quarter(const uint4 a, const uint4 b,
                                             const float* b1r, const float* w2r) {
    union { uint4 u; __half2 hh[4]; } ua, ub;
    ua.u = a; ub.u = b;
    float acc = 0.f;
    #pragma unroll
    for (int j = 0; j < 4; j++) {
        __half2 s = __hadd2(ua.hh[j], ub.hh[j]);
        float2 f = __half22float2(s);
        float h0 = fmaxf(f.x + b1r[2 * j], 0.f);
        float h1 = fmaxf(f.y + b1r[2 * j + 1], 0.f);
        acc = fmaf(h0, w2r[2 * j], acc);
        acc = fmaf(h1, w2r[2 * j + 1], acc);
    }
    return acc;
}

__global__ void __launch_bounds__(256) k4_edge_mlp(const float* __restrict__ b1,
                                                   const float* __restrict__ w2,
                                                   const float* __restrict__ b2,
                                                   float* __restrict__ out, int E) {
    int tid = blockIdx.x * blockDim.x + threadIdx.x;
    int q = tid & 3;
    float b1r[8], w2r[8];
    #pragma unroll
    for (int i = 0; i < 8; i++) {
        b1r[i] = __ldg(&b1[q * 8 + i]);
        w2r[i] = __ldg(&w2[q * 8 + i]);
    }
    float b2v = __ldg(&b2[0]);
    const unsigned FULL = 0xFFFFFFFFu;

    int nGroups = (gridDim.x * blockDim.x) >> 2;
    int nPairs = (E + 1) >> 1;

    for (int p = tid >> 2; p < nPairs; p += 2 * nGroups) {
        int pB = p + nGroups;
        bool hasB = pB < nPairs;
        int eA = 2 * p, eB = 2 * pB;

        int4 edA = __ldg((const int4*)(g_edge + eA));
        int4 edB = hasB ? __ldg((const int4*)(g_edge + eB)) : make_int4(0, 0, 0, 0);

        uint4 psA0 = *((const uint4*)(g_ps + (size_t)edA.x * 32) + q);
        uint4 pdA0 = *((const uint4*)(g_pd + (size_t)edA.y * 32) + q);
        uint4 psA1 = *((const uint4*)(g_ps + (size_t)edA.z * 32) + q);
        uint4 pdA1 = *((const uint4*)(g_pd + (size_t)edA.w * 32) + q);
        uint4 psB0 = *((const uint4*)(g_ps + (size_t)edB.x * 32) + q);
        uint4 pdB0 = *((const uint4*)(g_pd + (size_t)edB.y * 32) + q);
        uint4 psB1 = *((const uint4*)(g_ps + (size_t)edB.z * 32) + q);
        uint4 pdB1 = *((const uint4*)(g_pd + (size_t)edB.w * 32) + q);

        float vA0 = mlp_quarter(psA0, pdA0, b1r, w2r);
        float vA1 = mlp_quarter(psA1, pdA1, b1r, w2r);
        float vB0 = mlp_quarter(psB0, pdB0, b1r, w2r);
        float vB1 = mlp_quarter(psB1, pdB1, b1r, w2r);

        float a0 = vA0 + __shfl_xor_sync(FULL, vA0, 1);
        float a1 = vA1 + __shfl_xor_sync(FULL, vA1, 1);
        float mA = (q & 1) ? a1 : a0;
        mA += __shfl_xor_sync(FULL, mA, 2);

        float c0 = vB0 + __shfl_xor_sync(FULL, vB0, 1);
        float c1 = vB1 + __shfl_xor_sync(FULL, vB1, 1);
        float mB = (q & 1) ? c1 : c0;
        mB += __shfl_xor_sync(FULL, mB, 2);

        if (q < 2) {
            int e = eA + q;
            if (e < E) out[e] = (mA + b2v) * INV_TEMP;
            if (hasB) {
                int e2 = eB + q;
                if (e2 < E) out[e2] = (mB + b2v) * INV_TEMP;
            }
        }
    }
}

extern "C" void kernel_launch(void* const* d_in, const int* in_sizes, int n_in,
                              void* d_out, int out_size) {
    const float* x        = (const float*)d_in[0];
    const void*  ei       = d_in[1];
    const float* W        = (const float*)d_in[2];
    const float* att_src  = (const float*)d_in[3];
    const float* att_dst  = (const float*)d_in[4];
    const float* bias     = (const float*)d_in[5];
    const float* w1       = (const float*)d_in[6];
    const float* b1       = (const float*)d_in[7];
    const float* w2       = (const float*)d_in[8];
    const float* b2       = (const float*)d_in[9];
    float* out = (float*)d_out;

    int N = in_sizes[0] / 16;  // x is [N, 16]
    int E = in_sizes[1] / 2;   // edge_index is [2, E]
    int NB = (N + 1023) / 1024;

    kA_init_node<<<(N + 127) / 128, 128>>>((const int*)ei, x, W, att_src, att_dst, N);
    k0_pack<<<(E + 255) / 256, 256>>>(ei, E);
    k_scan<<<NB, 1024>>>(N, E);
    k_scatter<<<(E + 255) / 256, 256>>>(E);
    {
        long long T = (long long)N * 32;
        k2b_aggregate<<<(unsigned)((T + 255) / 256), 256>>>(bias, N);
    }
    k3_node_p<<<592, 256>>>(w1, N);
    k4_edge_mlp<<<1184, 256>>>(b1, w2, b2, out, E);
}

// round 8
// speedup vs baseline: 1.4374x; 1.0010x over previous
#include <cuda_runtime.h>
#include <cuda_fp16.h>

// Problem constants: N=100000, E=1600000, IN_C=16, HID=32, HEADS=2
#define MAXN 100000
#define MAXE 1600000
#define NEG 0.2f
#define INV_TEMP (1.0f / 0.7f)

// ---- device scratch (static; no allocations allowed) ----
__device__ __align__(16) __half g_xp[MAXN * 64];   // [N][64] projected features (fp16)
__device__ float g_asrc[MAXN * 2];                 // attention src logits per head
__device__ float g_adst[MAXN * 2];                 // attention dst logits per head
__device__ __align__(16) __half g_ps[MAXN * 32];   // h @ w1[0:32,:]  (fp16)
__device__ __align__(16) __half g_pd[MAXN * 32];   // h @ w1[32:64,:] (fp16)
__device__ __align__(16) int2 g_edge[MAXE];        // packed (src, dst)
__device__ __align__(16) int g_srcs[MAXE];         // CSR: src ids grouped by dst
__device__ int g_deg[MAXN];                        // in-degree histogram
__device__ int g_off[MAXN + 1];                    // CSR offsets
__device__ int g_cur[MAXN];                        // scatter cursors
__device__ int g_bsum[128];                        // scan block totals
__device__ int g_bflag[128];                       // scan publish flags
__device__ int g_is64;

// K_init: zero histogram + scan flags; thread 0 detects edge int width
__global__ void k_init(const int* __restrict__ ei_words, int N) {
    int i = blockIdx.x * blockDim.x + threadIdx.x;
    if (i < N) g_deg[i] = 0;
    if (i < 128) g_bflag[i] = 0;
    if (i == 0) {
        int nonzero = 0;
        #pragma unroll
        for (int j = 0; j < 64; j++)
            if (ei_words[2 * j + 1] != 0) nonzero++;
        g_is64 = (nonzero == 0) ? 1 : 0;
    }
}

// K0b: pack edges to int2 and build in-degree histogram
__global__ void k0_pack(const void* __restrict__ ei, int E) {
    int e = blockIdx.x * blockDim.x + threadIdx.x;
    if (e >= E) return;
    int s, d;
    if (g_is64) {
        const long long* p = (const long long*)ei;
        s = (int)p[e];
        d = (int)p[e + E];
    } else {
        const int* p = (const int*)ei;
        s = p[e];
        d = p[e + E];
    }
    g_edge[e] = make_int2(s, d);
    atomicAdd(&g_deg[d], 1);
}

// K_scan: single-kernel exclusive scan of g_deg -> g_off (+ cursor init,
// sentinel). Warp-shuffle block scan; cross-block base via parallel lookback
// (all <=98 blocks co-resident, so the spin always progresses).
__global__ void __launch_bounds__(1024) k_scan(int N, int E) {
    __shared__ int warpsums[32];
    __shared__ int sred[32];
    __shared__ int sbase;
    const unsigned FULL = 0xFFFFFFFFu;
    int tid = threadIdx.x;
    int lane = tid & 31, wid = tid >> 5;
    int b = blockIdx.x;
    int i = b * 1024 + tid;

    int v = (i < N) ? g_deg[i] : 0;
    int sc = v;
    #pragma unroll
    for (int ofs = 1; ofs < 32; ofs <<= 1) {
        int t = __shfl_up_sync(FULL, sc, ofs);
        if (lane >= ofs) sc += t;
    }
    if (lane == 31) warpsums[wid] = sc;
    __syncthreads();
    if (wid == 0) {
        int w = warpsums[lane];
        #pragma unroll
        for (int ofs = 1; ofs < 32; ofs <<= 1) {
            int t = __shfl_up_sync(FULL, w, ofs);
            if (lane >= ofs) w += t;
        }
        warpsums[lane] = w;
    }
    __syncthreads();
    int blockpref = (wid > 0) ? warpsums[wid - 1] : 0;
    int excl = sc + blockpref - v;
    int total = warpsums[31];

    if (tid == 0) {
        g_bsum[b] = total;
        __threadfence();
        atomicExch(&g_bflag[b], 1);
    }

    int part = 0;
    if (tid < b) {
        while (atomicAdd(&g_bflag[tid], 0) == 0) { }
        __threadfence();
        part = g_bsum[tid];
    }
    #pragma unroll
    for (int ofs = 16; ofs > 0; ofs >>= 1)
        part += __shfl_xor_sync(FULL, part, ofs);
    if (lane == 0) sred[wid] = part;
    __syncthreads();
    if (tid == 0) {
        int s = 0;
        #pragma unroll
        for (int k = 0; k < 4; k++) s += sred[k];
        sbase = s;
    }
    __syncthreads();
    int base = sbase;

    if (i < N) {
        int o = excl + base;
        g_off[i] = o;
        g_cur[i] = o;
    }
    if (b == 0 && tid == 0) g_off[N] = E;
}

// K_fused: blocks [0, nodeBlocks) do the node projection (xp = x@W, attention
// logits); remaining blocks scatter edges into the dst-grouped CSR. The two
// halves are independent; node FMAs fill the scatter's idle issue slots.
__global__ void __launch_bounds__(256) k_fused_scatter_node(
    const float* __restrict__ x, const float* __restrict__ W,
    const float* __restrict__ att_src, const float* __restrict__ att_dst,
    int N, int E, int nodeBlocks) {
    int tid = threadIdx.x;

    if (blockIdx.x >= (unsigned)nodeBlocks) {
        // ---- edge scatter part ----
        int e = (blockIdx.x - nodeBlocks) * blockDim.x + tid;
        if (e >= E) return;
        int2 sd = g_edge[e];
        int pos = atomicAdd(&g_cur[sd.y], 1);
        g_srcs[pos] = sd.x;
        return;
    }

    // ---- node projection part ----
    __shared__ float sW[16 * 64];
    __shared__ float sAs[64];
    __shared__ float sAd[64];
    for (int i = tid; i < 16 * 64; i += blockDim.x) sW[i] = W[i];
    if (tid < 64) { sAs[tid] = att_src[tid]; sAd[tid] = att_dst[tid]; }
    __syncthreads();

    int n = blockIdx.x * blockDim.x + tid;
    if (n >= N) return;

    float xv[16];
    const float4* x4 = (const float4*)(x + (size_t)n * 16);
    #pragma unroll
    for (int i = 0; i < 4; i++) {
        float4 t = x4[i];
        xv[4 * i + 0] = t.x; xv[4 * i + 1] = t.y;
        xv[4 * i + 2] = t.z; xv[4 * i + 3] = t.w;
    }

    float xp[64];
    float a0s = 0.f, a1s = 0.f, a0d = 0.f, a1d = 0.f;
    #pragma unroll
    for (int j = 0; j < 64; j++) {
        float v = 0.f;
        #pragma unroll
        for (int k = 0; k < 16; k++) v = fmaf(xv[k], sW[k * 64 + j], v);
        xp[j] = v;
        float as = sAs[j] * v;
        float ad = sAd[j] * v;
        if (j < 32) { a0s += as; a0d += ad; }
        else        { a1s += as; a1d += ad; }
    }

    g_asrc[n * 2 + 0] = a0s; g_asrc[n * 2 + 1] = a1s;
    g_adst[n * 2 + 0] = a0d; g_adst[n * 2 + 1] = a1d;

    union { uint4 u; __half2 h[4]; } pk;
    uint4* xpo = (uint4*)(g_xp + (size_t)n * 64);
    #pragma unroll
    for (int q = 0; q < 8; q++) {
        #pragma unroll
        for (int j = 0; j < 4; j++)
            pk.h[j] = __floats2half2_rn(xp[8 * q + 2 * j], xp[8 * q + 2 * j + 1]);
        xpo[q] = pk.u;
    }
}

// K2b3: warp-per-destination GAT aggregation + fused MLP layer-1 fold.
// Lane c owns channels {2c, 2c+1} (head = c/16); after the softmax-weighted
// aggregate, the warp computes ps/pd = h @ w1 via shfl broadcasts and shared
// w1, writing fp16 rows consumed by k4. No g_h round trip.
__global__ void __launch_bounds__(256) k2b3_aggregate(const float* __restrict__ bias,
                                                      const float* __restrict__ w1, int N) {
    __shared__ float sW1[64 * 32];
    int tid = threadIdx.x;
    for (int i = tid; i < 64 * 32; i += blockDim.x) sW1[i] = w1[i];
    __syncthreads();

    int n = (blockIdx.x * blockDim.x + tid) >> 5;
    if (n >= N) return;
    int c = tid & 31;
    int h = c >> 4;
    const unsigned FULL = 0xFFFFFFFFu;

    float adn = g_adst[n * 2 + h];
    float ee = g_asrc[n * 2 + h] + adn;           // self loop
    ee = ee > 0.f ? ee : NEG * ee;
    float w = __expf(ee);
    float2 xs = __half22float2(*(const __half2*)(g_xp + (size_t)n * 64 + 2 * c));
    float acc0 = w * xs.x, acc1 = w * xs.y, dsum = w;

    int i = g_off[n];
    int end = g_off[n + 1];

    for (; i + 8 <= end; i += 8) {
        int s[8];
        #pragma unroll
        for (int j = 0; j < 8; j++) s[j] = __ldg(&g_srcs[i + j]);
        float a[8];
        __half2 xh[8];
        #pragma unroll
        for (int j = 0; j < 8; j++) {
            a[j] = __ldg(&g_asrc[s[j] * 2 + h]);
            xh[j] = *(const __half2*)(g_xp + (size_t)s[j] * 64 + 2 * c);
        }
        #pragma unroll
        for (int j = 0; j < 8; j++) {
            float e0 = a[j] + adn; e0 = e0 > 0.f ? e0 : NEG * e0;
            float w0 = __expf(e0);
            dsum += w0;
            float2 f = __half22float2(xh[j]);
            acc0 = fmaf(w0, f.x, acc0);
            acc1 = fmaf(w0, f.y, acc1);
        }
    }
    for (; i + 2 <= end; i += 2) {
        int s0 = __ldg(&g_srcs[i]), s1 = __ldg(&g_srcs[i + 1]);
        float a0 = __ldg(&g_asrc[s0 * 2 + h]);
        float a1 = __ldg(&g_asrc[s1 * 2 + h]);
        __half2 x0 = *(const __half2*)(g_xp + (size_t)s0 * 64 + 2 * c);
        __half2 x1 = *(const __half2*)(g_xp + (size_t)s1 * 64 + 2 * c);
        float e0 = a0 + adn; e0 = e0 > 0.f ? e0 : NEG * e0;
        float e1 = a1 + adn; e1 = e1 > 0.f ? e1 : NEG * e1;
        float w0 = __expf(e0), w1v = __expf(e1);
        dsum += w0 + w1v;
        float2 f0 = __half22float2(x0);
        float2 f1 = __half22float2(x1);
        acc0 = fmaf(w0, f0.x, acc0);  acc1 = fmaf(w0, f0.y, acc1);
        acc0 = fmaf(w1v, f1.x, acc0); acc1 = fmaf(w1v, f1.y, acc1);
    }
    if (i < end) {
        int s = __ldg(&g_srcs[i]);
        float a = __ldg(&g_asrc[s * 2 + h]);
        __half2 xh = *(const __half2*)(g_xp + (size_t)s * 64 + 2 * c);
        float e0 = a + adn; e0 = e0 > 0.f ? e0 : NEG * e0;
        float w0 = __expf(e0);
        dsum += w0;
        float2 f = __half22float2(xh);
        acc0 = fmaf(w0, f.x, acc0);
        acc1 = fmaf(w0, f.y, acc1);
    }

    float d0 = __shfl_sync(FULL, dsum, 0);
    float d1 = __shfl_sync(FULL, dsum, 16);
    float p0 = __shfl_sync(FULL, acc0, (c + 16) & 31);
    float p1 = __shfl_sync(FULL, acc1, (c + 16) & 31);

    // head-mean + bias; valid on lanes 0..15 (channels 2c, 2c+1)
    int c15 = c & 15;
    float h0 = 0.5f * (acc0 / d0 + p0 / d1) + __ldg(&bias[2 * c15]);
    float h1 = 0.5f * (acc1 / d0 + p1 / d1) + __ldg(&bias[2 * c15 + 1]);

    // fused k3: ps/pd = h @ w1 (lane c computes output channel c)
    float ps = 0.f, pd = 0.f;
    #pragma unroll
    for (int k = 0; k < 16; k++) {
        float ha = __shfl_sync(FULL, h0, k);
        float hb = __shfl_sync(FULL, h1, k);
        ps = fmaf(ha, sW1[(2 * k) * 32 + c], ps);
        ps = fmaf(hb, sW1[(2 * k + 1) * 32 + c], ps);
        pd = fmaf(ha, sW1[(32 + 2 * k) * 32 + c], pd);
        pd = fmaf(hb, sW1[(32 + 2 * k + 1) * 32 + c], pd);
    }
    g_ps[(size_t)n * 32 + c] = __float2half_rn(ps);
    g_pd[(size_t)n * 32 + c] = __float2half_rn(pd);
}

// K4: per-edge MLP. 4-lane group per consecutive edge pair (one int4 edge
// load); two independent pairs in flight per thread. ps+pd summed in half2.
__device__ __forceinline__ float mlp_quarter(const uint4 a, const uint4 b,
                                             const float* b1r, const float* w2r) {
    union { uint4 u; __half2 hh[4]; } ua, ub;
    ua.u = a; ub.u = b;
    float acc = 0.f;
    #pragma unroll
    for (int j = 0; j < 4; j++) {
        __half2 s = __hadd2(ua.hh[j], ub.hh[j]);
        float2 f = __half22float2(s);
        float h0 = fmaxf(f.x + b1r[2 * j], 0.f);
        float h1 = fmaxf(f.y + b1r[2 * j + 1], 0.f);
        acc = fmaf(h0, w2r[2 * j], acc);
        acc = fmaf(h1, w2r[2 * j + 1], acc);
    }
    return acc;
}

__global__ void __launch_bounds__(256) k4_edge_mlp(const float* __restrict__ b1,
                                                   const float* __restrict__ w2,
                                                   const float* __restrict__ b2,
                                                   float* __restrict__ out, int E) {
    int tid = blockIdx.x * blockDim.x + threadIdx.x;
    int q = tid & 3;
    float b1r[8], w2r[8];
    #pragma unroll
    for (int i = 0; i < 8; i++) {
        b1r[i] = __ldg(&b1[q * 8 + i]);
        w2r[i] = __ldg(&w2[q * 8 + i]);
    }
    float b2v = __ldg(&b2[0]);
    const unsigned FULL = 0xFFFFFFFFu;

    int nGroups = (gridDim.x * blockDim.x) >> 2;
    int nPairs = (E + 1) >> 1;

    for (int p = tid >> 2; p < nPairs; p += 2 * nGroups) {
        int pB = p + nGroups;
        bool hasB = pB < nPairs;
        int eA = 2 * p, eB = 2 * pB;

        int4 edA = __ldg((const int4*)(g_edge + eA));
        int4 edB = hasB ? __ldg((const int4*)(g_edge + eB)) : make_int4(0, 0, 0, 0);

        uint4 psA0 = *((const uint4*)(g_ps + (size_t)edA.x * 32) + q);
        uint4 pdA0 = *((const uint4*)(g_pd + (size_t)edA.y * 32) + q);
        uint4 psA1 = *((const uint4*)(g_ps + (size_t)edA.z * 32) + q);
        uint4 pdA1 = *((const uint4*)(g_pd + (size_t)edA.w * 32) + q);
        uint4 psB0 = *((const uint4*)(g_ps + (size_t)edB.x * 32) + q);
        uint4 pdB0 = *((const uint4*)(g_pd + (size_t)edB.y * 32) + q);
        uint4 psB1 = *((const uint4*)(g_ps + (size_t)edB.z * 32) + q);
        uint4 pdB1 = *((const uint4*)(g_pd + (size_t)edB.w * 32) + q);

        float vA0 = mlp_quarter(psA0, pdA0, b1r, w2r);
        float vA1 = mlp_quarter(psA1, pdA1, b1r, w2r);
        float vB0 = mlp_quarter(psB0, pdB0, b1r, w2r);
        float vB1 = mlp_quarter(psB1, pdB1, b1r, w2r);

        float a0 = vA0 + __shfl_xor_sync(FULL, vA0, 1);
        float a1 = vA1 + __shfl_xor_sync(FULL, vA1, 1);
        float mA = (q & 1) ? a1 : a0;
        mA += __shfl_xor_sync(FULL, mA, 2);

        float c0 = vB0 + __shfl_xor_sync(FULL, vB0, 1);
        float c1 = vB1 + __shfl_xor_sync(FULL, vB1, 1);
        float mB = (q & 1) ? c1 : c0;
        mB += __shfl_xor_sync(FULL, mB, 2);

        if (q < 2) {
            int e = eA + q;
            if (e < E) out[e] = (mA + b2v) * INV_TEMP;
            if (hasB) {
                int e2 = eB + q;
                if (e2 < E) out[e2] = (mB + b2v) * INV_TEMP;
            }
        }
    }
}

extern "C" void kernel_launch(void* const* d_in, const int* in_sizes, int n_in,
                              void* d_out, int out_size) {
    const float* x        = (const float*)d_in[0];
    const void*  ei       = d_in[1];
    const float* W        = (const float*)d_in[2];
    const float* att_src  = (const float*)d_in[3];
    const float* att_dst  = (const float*)d_in[4];
    const float* bias     = (const float*)d_in[5];
    const float* w1       = (const float*)d_in[6];
    const float* b1       = (const float*)d_in[7];
    const float* w2       = (const float*)d_in[8];
    const float* b2       = (const float*)d_in[9];
    float* out = (float*)d_out;

    int N = in_sizes[0] / 16;  // x is [N, 16]
    int E = in_sizes[1] / 2;   // edge_index is [2, E]
    int NB = (N + 1023) / 1024;
    int nodeBlocks = (N + 255) / 256;
    int edgeBlocks = (E + 255) / 256;

    k_init<<<(N + 255) / 256, 256>>>((const int*)ei, N);
    k0_pack<<<edgeBlocks, 256>>>(ei, E);
    k_scan<<<NB, 1024>>>(N, E);
    k_fused_scatter_node<<<nodeBlocks + edgeBlocks, 256>>>(x, W, att_src, att_dst,
                                                           N, E, nodeBlocks);
    {
        long long T = (long long)N * 32;
        k2b3_aggregate<<<(unsigned)((T + 255) / 256), 256>>>(bias, w1, N);
    }
    k4_edge_mlp<<<1184, 256>>>(b1, w2, b2, out, E);
}

// round 9
// speedup vs baseline: 1.4734x; 1.0250x over previous
#include <cuda_runtime.h>
#include <cuda_fp16.h>

// Problem constants: N=100000, E=1600000, IN_C=16, HID=32, HEADS=2
#define MAXN 100000
#define MAXE 1600000
#define NEG 0.2f
#define INV_TEMP (1.0f / 0.7f)

// ---- device scratch (static; no allocations allowed) ----
__device__ __align__(16) __half g_xp[MAXN * 64];   // [N][64] projected features (fp16)
__device__ float g_asrc[MAXN * 2];                 // attention src logits per head
__device__ float g_adst[MAXN * 2];                 // attention dst logits per head
__device__ __align__(16) __half g_ps[MAXN * 32];   // h @ w1[0:32,:]  (fp16)
__device__ __align__(16) __half g_pd[MAXN * 32];   // h @ w1[32:64,:] (fp16)
__device__ __align__(16) int2 g_edge[MAXE];        // packed (src, dst)
__device__ __align__(16) int g_srcs[MAXE];         // CSR: src ids grouped by dst
__device__ int g_deg[MAXN];                        // in-degree histogram
__device__ int g_off[MAXN + 1];                    // CSR offsets
__device__ int g_cur[MAXN];                        // scatter cursors
__device__ int g_bsum[128];                        // scan block totals
__device__ int g_bflag[128];                       // scan publish flags
__device__ int g_is64;

// K_init: zero histogram + scan flags; thread 0 detects edge int width
__global__ void k_init(const int* __restrict__ ei_words, int N) {
    int i = blockIdx.x * blockDim.x + threadIdx.x;
    if (i < N) g_deg[i] = 0;
    if (i < 128) g_bflag[i] = 0;
    if (i == 0) {
        int nonzero = 0;
        #pragma unroll
        for (int j = 0; j < 64; j++)
            if (ei_words[2 * j + 1] != 0) nonzero++;
        g_is64 = (nonzero == 0) ? 1 : 0;
    }
}

// K0b: pack edges to int2 and build in-degree histogram
__global__ void k0_pack(const void* __restrict__ ei, int E) {
    int e = blockIdx.x * blockDim.x + threadIdx.x;
    if (e >= E) return;
    int s, d;
    if (g_is64) {
        const long long* p = (const long long*)ei;
        s = (int)p[e];
        d = (int)p[e + E];
    } else {
        const int* p = (const int*)ei;
        s = p[e];
        d = p[e + E];
    }
    g_edge[e] = make_int2(s, d);
    atomicAdd(&g_deg[d], 1);
}

// K_scan: single-kernel exclusive scan of g_deg -> g_off (+ cursor init,
// sentinel). Warp-shuffle block scan; cross-block base via parallel lookback
// (all <=98 blocks co-resident, so the spin always progresses).
__global__ void __launch_bounds__(1024) k_scan(int N, int E) {
    __shared__ int warpsums[32];
    __shared__ int sred[32];
    __shared__ int sbase;
    const unsigned FULL = 0xFFFFFFFFu;
    int tid = threadIdx.x;
    int lane = tid & 31, wid = tid >> 5;
    int b = blockIdx.x;
    int i = b * 1024 + tid;

    int v = (i < N) ? g_deg[i] : 0;
    int sc = v;
    #pragma unroll
    for (int ofs = 1; ofs < 32; ofs <<= 1) {
        int t = __shfl_up_sync(FULL, sc, ofs);
        if (lane >= ofs) sc += t;
    }
    if (lane == 31) warpsums[wid] = sc;
    __syncthreads();
    if (wid == 0) {
        int w = warpsums[lane];
        #pragma unroll
        for (int ofs = 1; ofs < 32; ofs <<= 1) {
            int t = __shfl_up_sync(FULL, w, ofs);
            if (lane >= ofs) w += t;
        }
        warpsums[lane] = w;
    }
    __syncthreads();
    int blockpref = (wid > 0) ? warpsums[wid - 1] : 0;
    int excl = sc + blockpref - v;
    int total = warpsums[31];

    if (tid == 0) {
        g_bsum[b] = total;
        __threadfence();
        atomicExch(&g_bflag[b], 1);
    }

    int part = 0;
    if (tid < b) {
        while (atomicAdd(&g_bflag[tid], 0) == 0) { }
        __threadfence();
        part = g_bsum[tid];
    }
    #pragma unroll
    for (int ofs = 16; ofs > 0; ofs >>= 1)
        part += __shfl_xor_sync(FULL, part, ofs);
    if (lane == 0) sred[wid] = part;
    __syncthreads();
    if (tid == 0) {
        int s = 0;
        #pragma unroll
        for (int k = 0; k < 4; k++) s += sred[k];
        sbase = s;
    }
    __syncthreads();
    int base = sbase;

    if (i < N) {
        int o = excl + base;
        g_off[i] = o;
        g_cur[i] = o;
    }
    if (b == 0 && tid == 0) g_off[N] = E;
}

// K_fused: blocks [0, nodeBlocks) do node projection; the rest scatter edges.
// Node projection is CHUNKED (16 output columns at a time) so it never holds
// all 64 outputs in registers -> low reg count -> scatter keeps occupancy.
__global__ void __launch_bounds__(256, 4) k_fused_scatter_node(
    const float* __restrict__ x, const float* __restrict__ W,
    const float* __restrict__ att_src, const float* __restrict__ att_dst,
    int N, int E, int nodeBlocks) {
    int tid = threadIdx.x;

    if (blockIdx.x >= (unsigned)nodeBlocks) {
        // ---- edge scatter part ----
        int e = (blockIdx.x - nodeBlocks) * blockDim.x + tid;
        if (e >= E) return;
        int2 sd = g_edge[e];
        int pos = atomicAdd(&g_cur[sd.y], 1);
        g_srcs[pos] = sd.x;
        return;
    }

    // ---- node projection part (chunked) ----
    __shared__ float sW[16 * 64];
    __shared__ float sAs[64];
    __shared__ float sAd[64];
    for (int i = tid; i < 16 * 64; i += blockDim.x) sW[i] = W[i];
    if (tid < 64) { sAs[tid] = att_src[tid]; sAd[tid] = att_dst[tid]; }
    __syncthreads();

    int n = blockIdx.x * blockDim.x + tid;
    if (n >= N) return;

    float xv[16];
    const float4* x4 = (const float4*)(x + (size_t)n * 16);
    #pragma unroll
    for (int i = 0; i < 4; i++) {
        float4 t = x4[i];
        xv[4 * i + 0] = t.x; xv[4 * i + 1] = t.y;
        xv[4 * i + 2] = t.z; xv[4 * i + 3] = t.w;
    }

    float hs[2] = {0.f, 0.f};   // attention src sums per head
    float hd[2] = {0.f, 0.f};   // attention dst sums per head
    uint4* xpo = (uint4*)(g_xp + (size_t)n * 64);

    #pragma unroll
    for (int ch = 0; ch < 4; ch++) {      // 4 chunks x 16 columns
        float v[16];
        float as = 0.f, ad = 0.f;
        #pragma unroll
        for (int jj = 0; jj < 16; jj++) {
            int j = ch * 16 + jj;
            float acc = 0.f;
            #pragma unroll
            for (int k = 0; k < 16; k++) acc = fmaf(xv[k], sW[k * 64 + j], acc);
            v[jj] = acc;
            as = fmaf(sAs[j], acc, as);
            ad = fmaf(sAd[j], acc, ad);
        }
        int hh = ch >> 1;
        hs[hh] += as;
        hd[hh] += ad;
        union { uint4 u; __half2 p[4]; } pk;
        #pragma unroll
        for (int g = 0; g < 2; g++) {
            #pragma unroll
            for (int j = 0; j < 4; j++)
                pk.p[j] = __floats2half2_rn(v[8 * g + 2 * j], v[8 * g + 2 * j + 1]);
            xpo[2 * ch + g] = pk.u;
        }
    }

    g_asrc[n * 2 + 0] = hs[0]; g_asrc[n * 2 + 1] = hs[1];
    g_adst[n * 2 + 0] = hd[0]; g_adst[n * 2 + 1] = hd[1];
}

// K2b3: warp-per-destination GAT aggregation + fused MLP layer-1 fold.
__global__ void __launch_bounds__(256) k2b3_aggregate(const float* __restrict__ bias,
                                                      const float* __restrict__ w1, int N) {
    __shared__ float sW1[64 * 32];
    int tid = threadIdx.x;
    for (int i = tid; i < 64 * 32; i += blockDim.x) sW1[i] = w1[i];
    __syncthreads();

    int n = (blockIdx.x * blockDim.x + tid) >> 5;
    if (n >= N) return;
    int c = tid & 31;
    int h = c >> 4;
    const unsigned FULL = 0xFFFFFFFFu;

    float adn = g_adst[n * 2 + h];
    float ee = g_asrc[n * 2 + h] + adn;           // self loop
    ee = ee > 0.f ? ee : NEG * ee;
    float w = __expf(ee);
    float2 xs = __half22float2(*(const __half2*)(g_xp + (size_t)n * 64 + 2 * c));
    float acc0 = w * xs.x, acc1 = w * xs.y, dsum = w;

    int i = g_off[n];
    int end = g_off[n + 1];

    for (; i + 8 <= end; i += 8) {
        int s[8];
        #pragma unroll
        for (int j = 0; j < 8; j++) s[j] = __ldg(&g_srcs[i + j]);
        float a[8];
        __half2 xh[8];
        #pragma unroll
        for (int j = 0; j < 8; j++) {
            a[j] = __ldg(&g_asrc[s[j] * 2 + h]);
            xh[j] = *(const __half2*)(g_xp + (size_t)s[j] * 64 + 2 * c);
        }
        #pragma unroll
        for (int j = 0; j < 8; j++) {
            float e0 = a[j] + adn; e0 = e0 > 0.f ? e0 : NEG * e0;
            float w0 = __expf(e0);
            dsum += w0;
            float2 f = __half22float2(xh[j]);
            acc0 = fmaf(w0, f.x, acc0);
            acc1 = fmaf(w0, f.y, acc1);
        }
    }
    for (; i + 2 <= end; i += 2) {
        int s0 = __ldg(&g_srcs[i]), s1 = __ldg(&g_srcs[i + 1]);
        float a0 = __ldg(&g_asrc[s0 * 2 + h]);
        float a1 = __ldg(&g_asrc[s1 * 2 + h]);
        __half2 x0 = *(const __half2*)(g_xp + (size_t)s0 * 64 + 2 * c);
        __half2 x1 = *(const __half2*)(g_xp + (size_t)s1 * 64 + 2 * c);
        float e0 = a0 + adn; e0 = e0 > 0.f ? e0 : NEG * e0;
        float e1 = a1 + adn; e1 = e1 > 0.f ? e1 : NEG * e1;
        float w0 = __expf(e0), w1v = __expf(e1);
        dsum += w0 + w1v;
        float2 f0 = __half22float2(x0);
        float2 f1 = __half22float2(x1);
        acc0 = fmaf(w0, f0.x, acc0);  acc1 = fmaf(w0, f0.y, acc1);
        acc0 = fmaf(w1v, f1.x, acc0); acc1 = fmaf(w1v, f1.y, acc1);
    }
    if (i < end) {
        int s = __ldg(&g_srcs[i]);
        float a = __ldg(&g_asrc[s * 2 + h]);
        __half2 xh = *(const __half2*)(g_xp + (size_t)s * 64 + 2 * c);
        float e0 = a + adn; e0 = e0 > 0.f ? e0 : NEG * e0;
        float w0 = __expf(e0);
        dsum += w0;
        float2 f = __half22float2(xh);
        acc0 = fmaf(w0, f.x, acc0);
        acc1 = fmaf(w0, f.y, acc1);
    }

    float d0 = __shfl_sync(FULL, dsum, 0);
    float d1 = __shfl_sync(FULL, dsum, 16);
    float p0 = __shfl_sync(FULL, acc0, (c + 16) & 31);
    float p1 = __shfl_sync(FULL, acc1, (c + 16) & 31);

    int c15 = c & 15;
    float h0 = 0.5f * (acc0 / d0 + p0 / d1) + __ldg(&bias[2 * c15]);
    float h1 = 0.5f * (acc1 / d0 + p1 / d1) + __ldg(&bias[2 * c15 + 1]);

    // fused k3: ps/pd = h @ w1 (lane c computes output channel c)
    float ps = 0.f, pd = 0.f;
    #pragma unroll
    for (int k = 0; k < 16; k++) {
        float ha = __shfl_sync(FULL, h0, k);
        float hb = __shfl_sync(FULL, h1, k);
        ps = fmaf(ha, sW1[(2 * k) * 32 + c], ps);
        ps = fmaf(hb, sW1[(2 * k + 1) * 32 + c], ps);
        pd = fmaf(ha, sW1[(32 + 2 * k) * 32 + c], pd);
        pd = fmaf(hb, sW1[(32 + 2 * k + 1) * 32 + c], pd);
    }
    g_ps[(size_t)n * 32 + c] = __float2half_rn(ps);
    g_pd[(size_t)n * 32 + c] = __float2half_rn(pd);
}

// K4: per-edge MLP. 4-lane group per consecutive edge pair (one int4 edge
// load); two independent pairs in flight per thread. ps+pd summed in half2.
__device__ __forceinline__ float mlp_quarter(const uint4 a, const uint4 b,
                                             const float* b1r, const float* w2r) {
    union { uint4 u; __half2 hh[4]; } ua, ub;
    ua.u = a; ub.u = b;
    float acc = 0.f;
    #pragma unroll
    for (int j = 0; j < 4; j++) {
        __half2 s = __hadd2(ua.hh[j], ub.hh[j]);
        float2 f = __half22float2(s);
        float h0 = fmaxf(f.x + b1r[2 * j], 0.f);
        float h1 = fmaxf(f.y + b1r[2 * j + 1], 0.f);
        acc = fmaf(h0, w2r[2 * j], acc);
        acc = fmaf(h1, w2r[2 * j + 1], acc);
    }
    return acc;
}

__global__ void __launch_bounds__(256) k4_edge_mlp(const float* __restrict__ b1,
                                                   const float* __restrict__ w2,
                                                   const float* __restrict__ b2,
                                                   float* __restrict__ out, int E) {
    int tid = blockIdx.x * blockDim.x + threadIdx.x;
    int q = tid & 3;
    float b1r[8], w2r[8];
    #pragma unroll
    for (int i = 0; i < 8; i++) {
        b1r[i] = __ldg(&b1[q * 8 + i]);
        w2r[i] = __ldg(&w2[q * 8 + i]);
    }
    float b2v = __ldg(&b2[0]);
    const unsigned FULL = 0xFFFFFFFFu;

    int nGroups = (gridDim.x * blockDim.x) >> 2;
    int nPairs = (E + 1) >> 1;

    for (int p = tid >> 2; p < nPairs; p += 2 * nGroups) {
        int pB = p + nGroups;
        bool hasB = pB < nPairs;
        int eA = 2 * p, eB = 2 * pB;

        int4 edA = __ldg((const int4*)(g_edge + eA));
        int4 edB = hasB ? __ldg((const int4*)(g_edge + eB)) : make_int4(0, 0, 0, 0);

        uint4 psA0 = *((const uint4*)(g_ps + (size_t)edA.x * 32) + q);
        uint4 pdA0 = *((const uint4*)(g_pd + (size_t)edA.y * 32) + q);
        uint4 psA1 = *((const uint4*)(g_ps + (size_t)edA.z * 32) + q);
        uint4 pdA1 = *((const uint4*)(g_pd + (size_t)edA.w * 32) + q);
        uint4 psB0 = *((const uint4*)(g_ps + (size_t)edB.x * 32) + q);
        uint4 pdB0 = *((const uint4*)(g_pd + (size_t)edB.y * 32) + q);
        uint4 psB1 = *((const uint4*)(g_ps + (size_t)edB.z * 32) + q);
        uint4 pdB1 = *((const uint4*)(g_pd + (size_t)edB.w * 32) + q);

        float vA0 = mlp_quarter(psA0, pdA0, b1r, w2r);
        float vA1 = mlp_quarter(psA1, pdA1, b1r, w2r);
        float vB0 = mlp_quarter(psB0, pdB0, b1r, w2r);
        float vB1 = mlp_quarter(psB1, pdB1, b1r, w2r);

        float a0 = vA0 + __shfl_xor_sync(FULL, vA0, 1);
        float a1 = vA1 + __shfl_xor_sync(FULL, vA1, 1);
        float mA = (q & 1) ? a1 : a0;
        mA += __shfl_xor_sync(FULL, mA, 2);

        float c0 = vB0 + __shfl_xor_sync(FULL, vB0, 1);
        float c1 = vB1 + __shfl_xor_sync(FULL, vB1, 1);
        float mB = (q & 1) ? c1 : c0;
        mB += __shfl_xor_sync(FULL, mB, 2);

        if (q < 2) {
            int e = eA + q;
            if (e < E) out[e] = (mA + b2v) * INV_TEMP;
            if (hasB) {
                int e2 = eB + q;
                if (e2 < E) out[e2] = (mB + b2v) * INV_TEMP;
            }
        }
    }
}

extern "C" void kernel_launch(void* const* d_in, const int* in_sizes, int n_in,
                              void* d_out, int out_size) {
    const float* x        = (const float*)d_in[0];
    const void*  ei       = d_in[1];
    const float* W        = (const float*)d_in[2];
    const float* att_src  = (const float*)d_in[3];
    const float* att_dst  = (const float*)d_in[4];
    const float* bias     = (const float*)d_in[5];
    const float* w1       = (const float*)d_in[6];
    const float* b1       = (const float*)d_in[7];
    const float* w2       = (const float*)d_in[8];
    const float* b2       = (const float*)d_in[9];
    float* out = (float*)d_out;

    int N = in_sizes[0] / 16;  // x is [N, 16]
    int E = in_sizes[1] / 2;   // edge_index is [2, E]
    int NB = (N + 1023) / 1024;
    int nodeBlocks = (N + 255) / 256;
    int edgeBlocks = (E + 255) / 256;

    k_init<<<(N + 255) / 256, 256>>>((const int*)ei, N);
    k0_pack<<<edgeBlocks, 256>>>(ei, E);
    k_scan<<<NB, 1024>>>(N, E);
    k_fused_scatter_node<<<nodeBlocks + edgeBlocks, 256>>>(x, W, att_src, att_dst,
                                                           N, E, nodeBlocks);
    {
        long long T = (long long)N * 32;
        k2b3_aggregate<<<(unsigned)((T + 255) / 256), 256>>>(bias, w1, N);
    }
    k4_edge_mlp<<<1184, 256>>>(b1, w2, b2, out, E);
}